// round 2
// baseline (speedup 1.0000x reference)
#include <cuda_runtime.h>
#include <cstdint>

#define NN 50000
#define NE 640000
#define DD 128

// ---------------- device scratch (no allocation allowed) ----------------
__device__ float g_ssrc[NN];
__device__ float g_sdst[NN];
__device__ float g_z[(size_t)NN * DD];
__device__ float g_h1[(size_t)NN * DD];
__device__ int   g_cnt[NN];
__device__ int   g_cur[NN];
__device__ int   g_rowstart[NN + 1];
__device__ int   g_csr[NE];

// ---------------- CSR build (dst is the same for both layers) ----------------
__global__ void k_zero_cnt() {
    int i = blockIdx.x * blockDim.x + threadIdx.x;
    if (i < NN) g_cnt[i] = 0;
}

__global__ void k_count(const int* __restrict__ dst) {
    int i = blockIdx.x * blockDim.x + threadIdx.x;
    if (i < NE) atomicAdd(&g_cnt[dst[i]], 1);
}

__global__ void k_scan() {
    __shared__ int sp[1024];
    const int t = threadIdx.x;
    const int C = (NN + 1023) / 1024;   // 49
    int base = t * C;
    int s = 0;
    for (int i = 0; i < C; i++) {
        int idx = base + i;
        if (idx < NN) s += g_cnt[idx];
    }
    sp[t] = s;
    __syncthreads();
    for (int off = 1; off < 1024; off <<= 1) {
        int v = (t >= off) ? sp[t - off] : 0;
        __syncthreads();
        sp[t] += v;
        __syncthreads();
    }
    int run = sp[t] - s;   // exclusive prefix of this chunk
    for (int i = 0; i < C; i++) {
        int idx = base + i;
        if (idx < NN) {
            int c = g_cnt[idx];
            g_rowstart[idx] = run;
            g_cur[idx] = run;
            run += c;
        }
    }
    if (t == 1023) g_rowstart[NN] = run;   // == NE
}

__global__ void k_fill(const int* __restrict__ dst) {
    int i = blockIdx.x * blockDim.x + threadIdx.x;
    if (i < NE) {
        int d = dst[i];
        int pos = atomicAdd(&g_cur[d], 1);
        g_csr[pos] = i;
    }
}

// ---------------- per-node partial attention dots ----------------
// s_src[n] = h[n]·aw[0:128],  s_dst[n] = h[n]·aw[128:256]
__global__ void k_node_dots(const float* __restrict__ H, const float* __restrict__ AW) {
    int gw   = (blockIdx.x * blockDim.x + threadIdx.x) >> 5;
    int lane = threadIdx.x & 31;
    if (gw >= NN) return;
    float4 hv = reinterpret_cast<const float4*>(H)[(size_t)gw * 32 + lane];
    float4 wl = reinterpret_cast<const float4*>(AW)[lane];
    float4 wh = reinterpret_cast<const float4*>(AW)[lane + 32];
    float ps = hv.x * wl.x + hv.y * wl.y + hv.z * wl.z + hv.w * wl.w;
    float pd = hv.x * wh.x + hv.y * wh.y + hv.z * wh.z + hv.w * wh.w;
    #pragma unroll
    for (int o = 16; o; o >>= 1) {
        ps += __shfl_xor_sync(0xffffffffu, ps, o);
        pd += __shfl_xor_sync(0xffffffffu, pd, o);
    }
    if (lane == 0) { g_ssrc[gw] = ps; g_sdst[gw] = pd; }
}

// ---------------- warp-per-node segment softmax + weighted gather of efeats ----------------
__global__ void k_softmax_z(const float* __restrict__ efeats,
                            const int*   __restrict__ src,
                            const float* __restrict__ attn_b) {
    int n    = (blockIdx.x * blockDim.x + threadIdx.x) >> 5;
    int lane = threadIdx.x & 31;
    if (n >= NN) return;
    const int beg = g_rowstart[n];
    const int end = g_rowstart[n + 1];
    const float sd = g_sdst[n];
    const float ab = __ldg(attn_b);

    // phase A: segment max of relu(logit)
    float m = -1e30f;
    for (int j = beg + lane; j < end; j += 32) {
        int eid  = g_csr[j];
        float ev = g_ssrc[src[eid]] + sd + ab;
        ev = ev > 0.f ? ev : 0.f;
        m = fmaxf(m, ev);
    }
    #pragma unroll
    for (int o = 16; o; o >>= 1) m = fmaxf(m, __shfl_xor_sync(0xffffffffu, m, o));

    // phase B: denom
    float den = 0.f;
    for (int j = beg + lane; j < end; j += 32) {
        int eid  = g_csr[j];
        float ev = g_ssrc[src[eid]] + sd + ab;
        ev = ev > 0.f ? ev : 0.f;
        den += __expf(ev - m);
    }
    #pragma unroll
    for (int o = 16; o; o >>= 1) den += __shfl_xor_sync(0xffffffffu, den, o);
    float invden = (end > beg) ? (1.0f / den) : 0.f;

    // phase C: z[n] = sum alpha_e * efeat[e]   (lanes parallel over feature dim)
    float4 acc = make_float4(0.f, 0.f, 0.f, 0.f);
    for (int j = beg; j < end; j++) {
        int eid  = g_csr[j];                       // uniform broadcast loads
        float ev = g_ssrc[src[eid]] + sd + ab;
        ev = ev > 0.f ? ev : 0.f;
        float alpha = __expf(ev - m) * invden;
        float4 ef = reinterpret_cast<const float4*>(efeats)[(size_t)eid * 32 + lane];
        acc.x = fmaf(alpha, ef.x, acc.x);
        acc.y = fmaf(alpha, ef.y, acc.y);
        acc.z = fmaf(alpha, ef.z, acc.z);
        acc.w = fmaf(alpha, ef.w, acc.w);
    }
    reinterpret_cast<float4*>(g_z)[(size_t)n * 32 + lane] = acc;
}

// ---------------- fused node-update GEMM: out = relu([H|Z] @ W^T + b) ----------------
// M=50000, N=128(all outputs), K=256.  BM=128, BN=128, BK=16, 8x8 micro-tiles.
__global__ __launch_bounds__(256) void k_gemm(const float* __restrict__ H,
                                              const float* __restrict__ Z,
                                              const float* __restrict__ W,
                                              const float* __restrict__ bias,
                                              float* __restrict__ out) {
    __shared__ float Xs[16][132];
    __shared__ float Ws[16][132];
    const int tid = threadIdx.x;
    const int tx  = tid & 15;
    const int ty  = tid >> 4;
    const int bm  = blockIdx.x * 128;

    float acc[8][8];
    #pragma unroll
    for (int i = 0; i < 8; i++)
        #pragma unroll
        for (int j = 0; j < 8; j++) acc[i][j] = 0.f;

    for (int kb = 0; kb < 256; kb += 16) {
        #pragma unroll
        for (int r = 0; r < 2; r++) {
            int f   = tid + r * 256;
            int row = f >> 2;        // 0..127
            int seg = f & 3;         // 0..3
            int k0  = kb + seg * 4;
            int m   = bm + row;
            if (m >= NN) m = NN - 1;
            const float* xsrc = (k0 < DD) ? (H + (size_t)m * DD + k0)
                                          : (Z + (size_t)m * DD + (k0 - DD));
            float4 xv = *reinterpret_cast<const float4*>(xsrc);
            Xs[seg * 4 + 0][row] = xv.x;
            Xs[seg * 4 + 1][row] = xv.y;
            Xs[seg * 4 + 2][row] = xv.z;
            Xs[seg * 4 + 3][row] = xv.w;
            float4 wv = *reinterpret_cast<const float4*>(W + row * 256 + k0);
            Ws[seg * 4 + 0][row] = wv.x;
            Ws[seg * 4 + 1][row] = wv.y;
            Ws[seg * 4 + 2][row] = wv.z;
            Ws[seg * 4 + 3][row] = wv.w;
        }
        __syncthreads();
        #pragma unroll
        for (int kk = 0; kk < 16; kk++) {
            float a[8], b[8];
            *reinterpret_cast<float4*>(&a[0]) = *reinterpret_cast<const float4*>(&Xs[kk][ty * 8]);
            *reinterpret_cast<float4*>(&a[4]) = *reinterpret_cast<const float4*>(&Xs[kk][ty * 8 + 4]);
            *reinterpret_cast<float4*>(&b[0]) = *reinterpret_cast<const float4*>(&Ws[kk][tx * 8]);
            *reinterpret_cast<float4*>(&b[4]) = *reinterpret_cast<const float4*>(&Ws[kk][tx * 8 + 4]);
            #pragma unroll
            for (int i = 0; i < 8; i++)
                #pragma unroll
                for (int j = 0; j < 8; j++) acc[i][j] = fmaf(a[i], b[j], acc[i][j]);
        }
        __syncthreads();
    }

    float bb[8];
    #pragma unroll
    for (int j = 0; j < 8; j++) bb[j] = bias[tx * 8 + j];
    #pragma unroll
    for (int i = 0; i < 8; i++) {
        int m = bm + ty * 8 + i;
        if (m < NN) {
            float4 o0, o1;
            o0.x = fmaxf(acc[i][0] + bb[0], 0.f);
            o0.y = fmaxf(acc[i][1] + bb[1], 0.f);
            o0.z = fmaxf(acc[i][2] + bb[2], 0.f);
            o0.w = fmaxf(acc[i][3] + bb[3], 0.f);
            o1.x = fmaxf(acc[i][4] + bb[4], 0.f);
            o1.y = fmaxf(acc[i][5] + bb[5], 0.f);
            o1.z = fmaxf(acc[i][6] + bb[6], 0.f);
            o1.w = fmaxf(acc[i][7] + bb[7], 0.f);
            *reinterpret_cast<float4*>(out + (size_t)m * DD + tx * 8)     = o0;
            *reinterpret_cast<float4*>(out + (size_t)m * DD + tx * 8 + 4) = o1;
        }
    }
}

// ---------------- launch ----------------
extern "C" void kernel_launch(void* const* d_in, const int* in_sizes, int n_in,
                              void* d_out, int out_size) {
    const float* nfeats = (const float*)d_in[0];
    const float* efeats = (const float*)d_in[1];
    const float* Ww0    = (const float*)d_in[2];
    const float* Wb0    = (const float*)d_in[3];
    const float* aw0    = (const float*)d_in[4];
    const float* ab0    = (const float*)d_in[5];
    const float* Ww1    = (const float*)d_in[6];
    const float* Wb1    = (const float*)d_in[7];
    const float* aw1    = (const float*)d_in[8];
    const float* ab1    = (const float*)d_in[9];
    const int*   src    = (const int*)d_in[10];
    const int*   dst    = (const int*)d_in[11];
    float* out = (float*)d_out;

    float* h1 = nullptr;
    float* z  = nullptr;
    cudaGetSymbolAddress((void**)&h1, g_h1);
    cudaGetSymbolAddress((void**)&z,  g_z);

    const int EB = (NE + 255) / 256;          // 2500
    const int NB = (NN + 255) / 256;          // 196
    const int WB = (NN + 7) / 8;              // 6250  (8 warps / 256-thread block)
    const int GB = (NN + 127) / 128;          // 391

    // CSR of incoming edges (shared by both layers)
    k_zero_cnt<<<NB, 256>>>();
    k_count<<<EB, 256>>>(dst);
    k_scan<<<1, 1024>>>();
    k_fill<<<EB, 256>>>(dst);

    // layer 1
    k_node_dots<<<WB, 256>>>(nfeats, aw0);
    k_softmax_z<<<WB, 256>>>(efeats, src, ab0);
    k_gemm<<<GB, 256>>>(nfeats, z, Ww0, Wb0, h1);

    // layer 2
    k_node_dots<<<WB, 256>>>(h1, aw1);
    k_softmax_z<<<WB, 256>>>(efeats, src, ab1);
    k_gemm<<<GB, 256>>>(h1, z, Ww1, Wb1, out);
}

// round 4
// speedup vs baseline: 1.3369x; 1.3369x over previous
#include <cuda_runtime.h>
#include <cuda_bf16.h>
#include <cstdint>

#define NN 50000
#define NE 640000
#define DD 128

// ---------------- device scratch ----------------
__device__ float g_ssrc[NN];
__device__ float g_sdst[NN];
__device__ float g_z[(size_t)NN * DD];
__device__ float g_h1[(size_t)NN * DD];
__device__ int   g_cnt[NN];
__device__ int   g_cur[NN];
__device__ int   g_rowstart[NN + 1];
__device__ int   g_csr[NE];
// bf16-split GEMM operands
__device__ __nv_bfloat16 g_xhi[(size_t)NN * 256];
__device__ __nv_bfloat16 g_xlo[(size_t)NN * 256];
__device__ __nv_bfloat16 g_whi0[128 * 256];
__device__ __nv_bfloat16 g_wlo0[128 * 256];
__device__ __nv_bfloat16 g_whi1[128 * 256];
__device__ __nv_bfloat16 g_wlo1[128 * 256];

// ---------------- helpers ----------------
__device__ __forceinline__ uint32_t smem_u32(const void* p) {
    uint32_t a;
    asm("{ .reg .u64 t; cvta.to.shared.u64 t, %1; cvt.u32.u64 %0, t; }" : "=r"(a) : "l"(p));
    return a;
}
__device__ __forceinline__ void cp16(uint32_t sdst, const void* gsrc) {
    asm volatile("cp.async.cg.shared.global [%0], [%1], 16;" :: "r"(sdst), "l"(gsrc));
}
__device__ __forceinline__ void cp_commit() {
    asm volatile("cp.async.commit_group;" ::: "memory");
}
template <int N>
__device__ __forceinline__ void cp_wait() {
    asm volatile("cp.async.wait_group %0;" :: "n"(N) : "memory");
}
__device__ __forceinline__ void ldsm_x4(uint32_t& r0, uint32_t& r1, uint32_t& r2, uint32_t& r3,
                                        uint32_t addr) {
    asm volatile("ldmatrix.sync.aligned.m8n8.x4.shared.b16 {%0,%1,%2,%3}, [%4];"
                 : "=r"(r0), "=r"(r1), "=r"(r2), "=r"(r3) : "r"(addr));
}
__device__ __forceinline__ void mma16816(float* c, const uint32_t* a, const uint32_t* b) {
    asm volatile(
        "mma.sync.aligned.m16n8k16.row.col.f32.bf16.bf16.f32 "
        "{%0,%1,%2,%3}, {%4,%5,%6,%7}, {%8,%9}, {%0,%1,%2,%3};"
        : "+f"(c[0]), "+f"(c[1]), "+f"(c[2]), "+f"(c[3])
        : "r"(a[0]), "r"(a[1]), "r"(a[2]), "r"(a[3]), "r"(b[0]), "r"(b[1]));
}

// ---------------- CSR build ----------------
__global__ void k_zero_cnt() {
    int i = blockIdx.x * blockDim.x + threadIdx.x;
    if (i < NN) g_cnt[i] = 0;
}
__global__ void k_count(const int* __restrict__ dst) {
    int i = blockIdx.x * blockDim.x + threadIdx.x;
    if (i < NE) atomicAdd(&g_cnt[dst[i]], 1);
}
__global__ void k_scan() {
    __shared__ int sp[1024];
    const int t = threadIdx.x;
    const int C = (NN + 1023) / 1024;
    int base = t * C;
    int s = 0;
    for (int i = 0; i < C; i++) {
        int idx = base + i;
        if (idx < NN) s += g_cnt[idx];
    }
    sp[t] = s;
    __syncthreads();
    for (int off = 1; off < 1024; off <<= 1) {
        int v = (t >= off) ? sp[t - off] : 0;
        __syncthreads();
        sp[t] += v;
        __syncthreads();
    }
    int run = sp[t] - s;
    for (int i = 0; i < C; i++) {
        int idx = base + i;
        if (idx < NN) {
            int c = g_cnt[idx];
            g_rowstart[idx] = run;
            g_cur[idx] = run;
            run += c;
        }
    }
    if (t == 1023) g_rowstart[NN] = run;
}
__global__ void k_fill(const int* __restrict__ dst) {
    int i = blockIdx.x * blockDim.x + threadIdx.x;
    if (i < NE) {
        int d = dst[i];
        int pos = atomicAdd(&g_cur[d], 1);
        g_csr[pos] = i;
    }
}

// ---------------- per-node partial attention dots ----------------
__global__ void k_node_dots(const float* __restrict__ H, const float* __restrict__ AW) {
    int gw   = (blockIdx.x * blockDim.x + threadIdx.x) >> 5;
    int lane = threadIdx.x & 31;
    if (gw >= NN) return;
    float4 hv = reinterpret_cast<const float4*>(H)[(size_t)gw * 32 + lane];
    float4 wl = reinterpret_cast<const float4*>(AW)[lane];
    float4 wh = reinterpret_cast<const float4*>(AW)[lane + 32];
    float ps = hv.x * wl.x + hv.y * wl.y + hv.z * wl.z + hv.w * wl.w;
    float pd = hv.x * wh.x + hv.y * wh.y + hv.z * wh.z + hv.w * wh.w;
    #pragma unroll
    for (int o = 16; o; o >>= 1) {
        ps += __shfl_xor_sync(0xffffffffu, ps, o);
        pd += __shfl_xor_sync(0xffffffffu, pd, o);
    }
    if (lane == 0) { g_ssrc[gw] = ps; g_sdst[gw] = pd; }
}

// ---------------- warp-per-node segment softmax + weighted gather ----------------
__global__ void k_softmax_z(const float* __restrict__ efeats,
                            const int*   __restrict__ src,
                            const float* __restrict__ attn_b) {
    int n    = (blockIdx.x * blockDim.x + threadIdx.x) >> 5;
    int lane = threadIdx.x & 31;
    if (n >= NN) return;
    const int beg = g_rowstart[n];
    const int end = g_rowstart[n + 1];
    const float sd = g_sdst[n];
    const float ab = __ldg(attn_b);

    float m = -1e30f;
    for (int j = beg + lane; j < end; j += 32) {
        int eid  = g_csr[j];
        float ev = g_ssrc[src[eid]] + sd + ab;
        ev = ev > 0.f ? ev : 0.f;
        m = fmaxf(m, ev);
    }
    #pragma unroll
    for (int o = 16; o; o >>= 1) m = fmaxf(m, __shfl_xor_sync(0xffffffffu, m, o));

    float den = 0.f;
    for (int j = beg + lane; j < end; j += 32) {
        int eid  = g_csr[j];
        float ev = g_ssrc[src[eid]] + sd + ab;
        ev = ev > 0.f ? ev : 0.f;
        den += __expf(ev - m);
    }
    #pragma unroll
    for (int o = 16; o; o >>= 1) den += __shfl_xor_sync(0xffffffffu, den, o);
    float invden = (end > beg) ? (1.0f / den) : 0.f;

    float4 acc = make_float4(0.f, 0.f, 0.f, 0.f);
    for (int j = beg; j < end; j++) {
        int eid  = g_csr[j];
        float ev = g_ssrc[src[eid]] + sd + ab;
        ev = ev > 0.f ? ev : 0.f;
        float alpha = __expf(ev - m) * invden;
        float4 ef = reinterpret_cast<const float4*>(efeats)[(size_t)eid * 32 + lane];
        acc.x = fmaf(alpha, ef.x, acc.x);
        acc.y = fmaf(alpha, ef.y, acc.y);
        acc.z = fmaf(alpha, ef.z, acc.z);
        acc.w = fmaf(alpha, ef.w, acc.w);
    }
    reinterpret_cast<float4*>(g_z)[(size_t)n * 32 + lane] = acc;
}

// ---------------- bf16 hi/lo split conversions ----------------
__global__ void k_conv_x(const float* __restrict__ H) {
    int idx = blockIdx.x * blockDim.x + threadIdx.x;
    if (idx >= NN * 64) return;
    int row = idx >> 6;
    int j   = idx & 63;
    float4 v = (j < 32)
        ? reinterpret_cast<const float4*>(H)[(size_t)row * 32 + j]
        : reinterpret_cast<const float4*>(g_z)[(size_t)row * 32 + (j - 32)];
    __nv_bfloat16 h0 = __float2bfloat16(v.x);
    __nv_bfloat16 h1 = __float2bfloat16(v.y);
    __nv_bfloat16 h2 = __float2bfloat16(v.z);
    __nv_bfloat16 h3 = __float2bfloat16(v.w);
    __nv_bfloat16 l0 = __float2bfloat16(v.x - __bfloat162float(h0));
    __nv_bfloat16 l1 = __float2bfloat16(v.y - __bfloat162float(h1));
    __nv_bfloat16 l2 = __float2bfloat16(v.z - __bfloat162float(h2));
    __nv_bfloat16 l3 = __float2bfloat16(v.w - __bfloat162float(h3));
    size_t o = (size_t)row * 256 + j * 4;
    reinterpret_cast<__nv_bfloat162*>(g_xhi + o)[0] = __halves2bfloat162(h0, h1);
    reinterpret_cast<__nv_bfloat162*>(g_xhi + o)[1] = __halves2bfloat162(h2, h3);
    reinterpret_cast<__nv_bfloat162*>(g_xlo + o)[0] = __halves2bfloat162(l0, l1);
    reinterpret_cast<__nv_bfloat162*>(g_xlo + o)[1] = __halves2bfloat162(l2, l3);
}

__global__ void k_conv_w(const float* __restrict__ W, __nv_bfloat16* __restrict__ hi,
                         __nv_bfloat16* __restrict__ lo) {
    int idx = blockIdx.x * blockDim.x + threadIdx.x;
    if (idx >= 128 * 64) return;
    float4 v = reinterpret_cast<const float4*>(W)[idx];
    __nv_bfloat16 h0 = __float2bfloat16(v.x);
    __nv_bfloat16 h1 = __float2bfloat16(v.y);
    __nv_bfloat16 h2 = __float2bfloat16(v.z);
    __nv_bfloat16 h3 = __float2bfloat16(v.w);
    __nv_bfloat16 l0 = __float2bfloat16(v.x - __bfloat162float(h0));
    __nv_bfloat16 l1 = __float2bfloat16(v.y - __bfloat162float(h1));
    __nv_bfloat16 l2 = __float2bfloat16(v.z - __bfloat162float(h2));
    __nv_bfloat16 l3 = __float2bfloat16(v.w - __bfloat162float(h3));
    size_t o = (size_t)idx * 4;
    reinterpret_cast<__nv_bfloat162*>(hi + o)[0] = __halves2bfloat162(h0, h1);
    reinterpret_cast<__nv_bfloat162*>(hi + o)[1] = __halves2bfloat162(h2, h3);
    reinterpret_cast<__nv_bfloat162*>(lo + o)[0] = __halves2bfloat162(l0, l1);
    reinterpret_cast<__nv_bfloat162*>(lo + o)[1] = __halves2bfloat162(l2, l3);
}

// ---------------- mma.sync bf16-split GEMM ----------------
// out[128-tile rows, 128 cols] = relu( Xhi*Whi^T + Xlo*Whi^T + Xhi*Wlo^T + b )
// BM=128, BN=128, BK=64, 8 warps (4 in M x 2 in N), warp tile 32x64.
// smem tiles: 128 rows x 64 bf16, row stride 144B (pad) -> conflict-free ldmatrix.
static constexpr int ROWB   = 144;                // padded row bytes
static constexpr int TILE_B = 128 * ROWB;         // 18432
static constexpr int STAGE_B = 4 * TILE_B;        // Ahi, Alo, Bhi, Blo
static constexpr int GSMEM  = 2 * STAGE_B;        // 147456

__global__ __launch_bounds__(256) void k_gemm_mma(const __nv_bfloat16* __restrict__ whi,
                                                  const __nv_bfloat16* __restrict__ wlo,
                                                  const float* __restrict__ bias,
                                                  float* __restrict__ out) {
    extern __shared__ char smem[];
    const uint32_t sb = smem_u32(smem);
    const int tid  = threadIdx.x;
    const int wid  = tid >> 5;
    const int lane = tid & 31;
    const int bm   = blockIdx.x * 128;
    const int wm   = (wid & 3) * 32;
    const int wn   = (wid >> 2) * 64;

    float c[2][8][4];
    #pragma unroll
    for (int i = 0; i < 2; i++)
        #pragma unroll
        for (int j = 0; j < 8; j++)
            #pragma unroll
            for (int k = 0; k < 4; k++) c[i][j][k] = 0.f;

    // per-thread load coords: 1024 16B-groups per tile / 256 thr = 4 each
    // idx = tid + 256*j : row = idx>>3, grp = idx&7
    auto load_chunk = [&](int kb, int st) {
        const uint32_t base = sb + st * STAGE_B;
        #pragma unroll
        for (int j = 0; j < 4; j++) {
            int idx = tid + j * 256;
            int row = idx >> 3;
            int grp = idx & 7;
            uint32_t soff = (uint32_t)(row * ROWB + grp * 16);
            int rg = bm + row;
            if (rg >= NN) rg = NN - 1;
            size_t ga = (size_t)rg * 256 + kb * 64 + grp * 8;
            cp16(base + 0 * TILE_B + soff, g_xhi + ga);
            cp16(base + 1 * TILE_B + soff, g_xlo + ga);
            size_t gw = (size_t)row * 256 + kb * 64 + grp * 8;
            cp16(base + 2 * TILE_B + soff, whi + gw);
            cp16(base + 3 * TILE_B + soff, wlo + gw);
        }
        cp_commit();
    };

    load_chunk(0, 0);

    const int g  = lane >> 3;      // ldmatrix address group 0..3
    const int l7 = lane & 7;

    #pragma unroll
    for (int kb = 0; kb < 4; kb++) {
        const int st = kb & 1;
        if (kb < 3) {
            load_chunk(kb + 1, st ^ 1);
            cp_wait<1>();
        } else {
            cp_wait<0>();
        }
        __syncthreads();

        const uint32_t baseA = sb + st * STAGE_B;
        const uint32_t baseB = baseA + 2 * TILE_B;

        #pragma unroll
        for (int ks = 0; ks < 4; ks++) {
            const int k0 = ks * 16;
            uint32_t ahi[2][4], alo[2][4], bhi[8][2], blo[8][2];

            #pragma unroll
            for (int mi = 0; mi < 2; mi++) {
                int row = wm + mi * 16 + (g & 1) * 8 + l7;
                uint32_t kbyte = (uint32_t)((k0 + (g >> 1) * 8) * 2);
                uint32_t off = (uint32_t)(row * ROWB) + kbyte;
                ldsm_x4(ahi[mi][0], ahi[mi][1], ahi[mi][2], ahi[mi][3], baseA + off);
                ldsm_x4(alo[mi][0], alo[mi][1], alo[mi][2], alo[mi][3], baseA + TILE_B + off);
            }
            #pragma unroll
            for (int j2 = 0; j2 < 4; j2++) {
                int row = wn + j2 * 16 + (g >> 1) * 8 + l7;
                uint32_t kbyte = (uint32_t)((k0 + (g & 1) * 8) * 2);
                uint32_t off = (uint32_t)(row * ROWB) + kbyte;
                uint32_t r0, r1, r2, r3;
                ldsm_x4(r0, r1, r2, r3, baseB + off);
                bhi[2 * j2][0] = r0; bhi[2 * j2][1] = r1;
                bhi[2 * j2 + 1][0] = r2; bhi[2 * j2 + 1][1] = r3;
                ldsm_x4(r0, r1, r2, r3, baseB + TILE_B + off);
                blo[2 * j2][0] = r0; blo[2 * j2][1] = r1;
                blo[2 * j2 + 1][0] = r2; blo[2 * j2 + 1][1] = r3;
            }

            #pragma unroll
            for (int mi = 0; mi < 2; mi++)
                #pragma unroll
                for (int nj = 0; nj < 8; nj++) {
                    mma16816(c[mi][nj], ahi[mi], bhi[nj]);
                    mma16816(c[mi][nj], alo[mi], bhi[nj]);
                    mma16816(c[mi][nj], ahi[mi], blo[nj]);
                }
        }
        __syncthreads();
    }

    // epilogue: bias + relu, fp32 stores
    #pragma unroll
    for (int mi = 0; mi < 2; mi++) {
        int m0 = bm + wm + mi * 16 + (lane >> 2);
        #pragma unroll
        for (int r = 0; r < 2; r++) {
            int m = m0 + 8 * r;
            if (m < NN) {
                #pragma unroll
                for (int nj = 0; nj < 8; nj++) {
                    int n = wn + nj * 8 + (lane & 3) * 2;
                    float2 bv = *reinterpret_cast<const float2*>(bias + n);
                    float2 o;
                    o.x = fmaxf(c[mi][nj][2 * r + 0] + bv.x, 0.f);
                    o.y = fmaxf(c[mi][nj][2 * r + 1] + bv.y, 0.f);
                    *reinterpret_cast<float2*>(out + (size_t)m * DD + n) = o;
                }
            }
        }
    }
}

// ---------------- launch ----------------
extern "C" void kernel_launch(void* const* d_in, const int* in_sizes, int n_in,
                              void* d_out, int out_size) {
    const float* nfeats = (const float*)d_in[0];
    const float* efeats = (const float*)d_in[1];
    const float* Ww0    = (const float*)d_in[2];
    const float* Wb0    = (const float*)d_in[3];
    const float* aw0    = (const float*)d_in[4];
    const float* ab0    = (const float*)d_in[5];
    const float* Ww1    = (const float*)d_in[6];
    const float* Wb1    = (const float*)d_in[7];
    const float* aw1    = (const float*)d_in[8];
    const float* ab1    = (const float*)d_in[9];
    const int*   src    = (const int*)d_in[10];
    const int*   dst    = (const int*)d_in[11];
    float* out = (float*)d_out;

    float* h1 = nullptr;
    cudaGetSymbolAddress((void**)&h1, g_h1);
    __nv_bfloat16 *whi0, *wlo0, *whi1, *wlo1;
    cudaGetSymbolAddress((void**)&whi0, g_whi0);
    cudaGetSymbolAddress((void**)&wlo0, g_wlo0);
    cudaGetSymbolAddress((void**)&whi1, g_whi1);
    cudaGetSymbolAddress((void**)&wlo1, g_wlo1);

    static bool attr_done = false;
    if (!attr_done) {
        cudaFuncSetAttribute(k_gemm_mma, cudaFuncAttributeMaxDynamicSharedMemorySize, GSMEM);
        attr_done = true;
    }

    const int EB = (NE + 255) / 256;
    const int NB = (NN + 255) / 256;
    const int WB = (NN + 7) / 8;
    const int GB = (NN + 127) / 128;          // 391
    const int CXB = (NN * 64 + 255) / 256;
    const int CWB = (128 * 64 + 255) / 256;

    // CSR of incoming edges (shared by both layers)
    k_zero_cnt<<<NB, 256>>>();
    k_count<<<EB, 256>>>(dst);
    k_scan<<<1, 1024>>>();
    k_fill<<<EB, 256>>>(dst);

    // weight splits
    k_conv_w<<<CWB, 256>>>(Ww0, whi0, wlo0);
    k_conv_w<<<CWB, 256>>>(Ww1, whi1, wlo1);

    // layer 1
    k_node_dots<<<WB, 256>>>(nfeats, aw0);
    k_softmax_z<<<WB, 256>>>(efeats, src, ab0);
    k_conv_x<<<CXB, 256>>>(nfeats);
    k_gemm_mma<<<GB, 256, GSMEM>>>(whi0, wlo0, Wb0, h1);

    // layer 2
    k_node_dots<<<WB, 256>>>(h1, aw1);
    k_softmax_z<<<WB, 256>>>(efeats, src, ab1);
    k_conv_x<<<CXB, 256>>>(h1);
    k_gemm_mma<<<GB, 256, GSMEM>>>(whi1, wlo1, Wb1, out);
}

// round 5
// speedup vs baseline: 1.3750x; 1.0285x over previous
#include <cuda_runtime.h>
#include <cuda_bf16.h>
#include <cstdint>

#define NN 50000
#define NE 640000
#define DD 128

// ---------------- device scratch ----------------
__device__ float g_ssrc[NN];
__device__ float g_sdst[NN];
__device__ float g_h1[(size_t)NN * DD];
__device__ float g_elog[NE];
__device__ int   g_cnt[NN];
__device__ int   g_cur[NN];
__device__ int   g_rowstart[NN + 1];
__device__ int   g_csr[NE];
// bf16-split GEMM operands: [N, 256] rows = [H(0:128) | Z(128:256)]
__device__ __nv_bfloat16 g_xhi[(size_t)NN * 256];
__device__ __nv_bfloat16 g_xlo[(size_t)NN * 256];
__device__ __nv_bfloat16 g_whi0[128 * 256];
__device__ __nv_bfloat16 g_wlo0[128 * 256];
__device__ __nv_bfloat16 g_whi1[128 * 256];
__device__ __nv_bfloat16 g_wlo1[128 * 256];

// ---------------- helpers ----------------
__device__ __forceinline__ uint32_t smem_u32(const void* p) {
    uint32_t a;
    asm("{ .reg .u64 t; cvta.to.shared.u64 t, %1; cvt.u32.u64 %0, t; }" : "=r"(a) : "l"(p));
    return a;
}
__device__ __forceinline__ void cp16(uint32_t sdst, const void* gsrc) {
    asm volatile("cp.async.cg.shared.global [%0], [%1], 16;" :: "r"(sdst), "l"(gsrc));
}
__device__ __forceinline__ void cp_commit() {
    asm volatile("cp.async.commit_group;" ::: "memory");
}
template <int N>
__device__ __forceinline__ void cp_wait() {
    asm volatile("cp.async.wait_group %0;" :: "n"(N) : "memory");
}
__device__ __forceinline__ void ldsm_x4(uint32_t& r0, uint32_t& r1, uint32_t& r2, uint32_t& r3,
                                        uint32_t addr) {
    asm volatile("ldmatrix.sync.aligned.m8n8.x4.shared.b16 {%0,%1,%2,%3}, [%4];"
                 : "=r"(r0), "=r"(r1), "=r"(r2), "=r"(r3) : "r"(addr));
}
__device__ __forceinline__ void mma16816(float* c, const uint32_t* a, const uint32_t* b) {
    asm volatile(
        "mma.sync.aligned.m16n8k16.row.col.f32.bf16.bf16.f32 "
        "{%0,%1,%2,%3}, {%4,%5,%6,%7}, {%8,%9}, {%0,%1,%2,%3};"
        : "+f"(c[0]), "+f"(c[1]), "+f"(c[2]), "+f"(c[3])
        : "r"(a[0]), "r"(a[1]), "r"(a[2]), "r"(a[3]), "r"(b[0]), "r"(b[1]));
}

// ---------------- CSR build ----------------
__global__ void k_zero_cnt() {
    int i = blockIdx.x * blockDim.x + threadIdx.x;
    if (i < NN) g_cnt[i] = 0;
}
__global__ void k_count4(const int* __restrict__ dst) {
    int i = blockIdx.x * blockDim.x + threadIdx.x;
    if (i < NE / 4) {
        int4 d = reinterpret_cast<const int4*>(dst)[i];
        atomicAdd(&g_cnt[d.x], 1);
        atomicAdd(&g_cnt[d.y], 1);
        atomicAdd(&g_cnt[d.z], 1);
        atomicAdd(&g_cnt[d.w], 1);
    }
}
__global__ void k_scan() {
    __shared__ int sp[1024];
    const int t = threadIdx.x;
    const int C = (NN + 1023) / 1024;
    int base = t * C;
    int s = 0;
    for (int i = 0; i < C; i++) {
        int idx = base + i;
        if (idx < NN) s += g_cnt[idx];
    }
    sp[t] = s;
    __syncthreads();
    for (int off = 1; off < 1024; off <<= 1) {
        int v = (t >= off) ? sp[t - off] : 0;
        __syncthreads();
        sp[t] += v;
        __syncthreads();
    }
    int run = sp[t] - s;
    for (int i = 0; i < C; i++) {
        int idx = base + i;
        if (idx < NN) {
            int c = g_cnt[idx];
            g_rowstart[idx] = run;
            g_cur[idx] = run;
            run += c;
        }
    }
    if (t == 1023) g_rowstart[NN] = run;
}
__global__ void k_fill4(const int* __restrict__ dst) {
    int i = blockIdx.x * blockDim.x + threadIdx.x;
    if (i < NE / 4) {
        int4 d = reinterpret_cast<const int4*>(dst)[i];
        int e = i * 4;
        int p0 = atomicAdd(&g_cur[d.x], 1);
        int p1 = atomicAdd(&g_cur[d.y], 1);
        int p2 = atomicAdd(&g_cur[d.z], 1);
        int p3 = atomicAdd(&g_cur[d.w], 1);
        g_csr[p0] = e;
        g_csr[p1] = e + 1;
        g_csr[p2] = e + 2;
        g_csr[p3] = e + 3;
    }
}

// ---------------- per-node partial attention dots ----------------
__global__ void k_node_dots(const float* __restrict__ H, const float* __restrict__ AW) {
    int gw   = (blockIdx.x * blockDim.x + threadIdx.x) >> 5;
    int lane = threadIdx.x & 31;
    if (gw >= NN) return;
    float4 hv = reinterpret_cast<const float4*>(H)[(size_t)gw * 32 + lane];
    float4 wl = reinterpret_cast<const float4*>(AW)[lane];
    float4 wh = reinterpret_cast<const float4*>(AW)[lane + 32];
    float ps = hv.x * wl.x + hv.y * wl.y + hv.z * wl.z + hv.w * wl.w;
    float pd = hv.x * wh.x + hv.y * wh.y + hv.z * wh.z + hv.w * wh.w;
    #pragma unroll
    for (int o = 16; o; o >>= 1) {
        ps += __shfl_xor_sync(0xffffffffu, ps, o);
        pd += __shfl_xor_sync(0xffffffffu, pd, o);
    }
    if (lane == 0) { g_ssrc[gw] = ps; g_sdst[gw] = pd; }
}

// ---------------- CSR-ordered relu logits ----------------
__global__ void k_elog(const int* __restrict__ src, const int* __restrict__ dst,
                       const float* __restrict__ attn_b) {
    int j = blockIdx.x * blockDim.x + threadIdx.x;
    if (j >= NE) return;
    int eid = g_csr[j];
    float e = g_ssrc[src[eid]] + g_sdst[dst[eid]] + __ldg(attn_b);
    g_elog[j] = e > 0.f ? e : 0.f;
}

// ---------------- warp-per-node segment softmax + weighted gather ----------------
// writes z as bf16 hi/lo into xhi/xlo cols 128..255
__global__ void k_softmax_z(const float* __restrict__ efeats) {
    int n    = (blockIdx.x * blockDim.x + threadIdx.x) >> 5;
    int lane = threadIdx.x & 31;
    if (n >= NN) return;
    const int beg = g_rowstart[n];
    const int end = g_rowstart[n + 1];

    float m = -1e30f;
    for (int j = beg + lane; j < end; j += 32) m = fmaxf(m, g_elog[j]);
    #pragma unroll
    for (int o = 16; o; o >>= 1) m = fmaxf(m, __shfl_xor_sync(0xffffffffu, m, o));

    float den = 0.f;
    for (int j = beg + lane; j < end; j += 32) {
        float ex = __expf(g_elog[j] - m);
        den += ex;
        g_elog[j] = ex;
    }
    #pragma unroll
    for (int o = 16; o; o >>= 1) den += __shfl_xor_sync(0xffffffffu, den, o);
    float invden = (end > beg) ? (1.0f / den) : 0.f;
    __syncwarp();

    float4 acc  = make_float4(0.f, 0.f, 0.f, 0.f);
    float4 acc2 = make_float4(0.f, 0.f, 0.f, 0.f);
    int j = beg;
    for (; j + 2 <= end; j += 2) {
        float a0 = g_elog[j] * invden;
        float a1 = g_elog[j + 1] * invden;
        int e0 = g_csr[j];
        int e1 = g_csr[j + 1];
        float4 f0 = reinterpret_cast<const float4*>(efeats)[(size_t)e0 * 32 + lane];
        float4 f1 = reinterpret_cast<const float4*>(efeats)[(size_t)e1 * 32 + lane];
        acc.x = fmaf(a0, f0.x, acc.x);   acc.y = fmaf(a0, f0.y, acc.y);
        acc.z = fmaf(a0, f0.z, acc.z);   acc.w = fmaf(a0, f0.w, acc.w);
        acc2.x = fmaf(a1, f1.x, acc2.x); acc2.y = fmaf(a1, f1.y, acc2.y);
        acc2.z = fmaf(a1, f1.z, acc2.z); acc2.w = fmaf(a1, f1.w, acc2.w);
    }
    if (j < end) {
        float a0 = g_elog[j] * invden;
        int e0 = g_csr[j];
        float4 f0 = reinterpret_cast<const float4*>(efeats)[(size_t)e0 * 32 + lane];
        acc.x = fmaf(a0, f0.x, acc.x); acc.y = fmaf(a0, f0.y, acc.y);
        acc.z = fmaf(a0, f0.z, acc.z); acc.w = fmaf(a0, f0.w, acc.w);
    }
    acc.x += acc2.x; acc.y += acc2.y; acc.z += acc2.z; acc.w += acc2.w;

    __nv_bfloat16 h0 = __float2bfloat16(acc.x);
    __nv_bfloat16 h1 = __float2bfloat16(acc.y);
    __nv_bfloat16 h2 = __float2bfloat16(acc.z);
    __nv_bfloat16 h3 = __float2bfloat16(acc.w);
    __nv_bfloat16 l0 = __float2bfloat16(acc.x - __bfloat162float(h0));
    __nv_bfloat16 l1 = __float2bfloat16(acc.y - __bfloat162float(h1));
    __nv_bfloat16 l2 = __float2bfloat16(acc.z - __bfloat162float(h2));
    __nv_bfloat16 l3 = __float2bfloat16(acc.w - __bfloat162float(h3));
    size_t o = (size_t)n * 256 + 128 + lane * 4;
    reinterpret_cast<__nv_bfloat162*>(g_xhi + o)[0] = __halves2bfloat162(h0, h1);
    reinterpret_cast<__nv_bfloat162*>(g_xhi + o)[1] = __halves2bfloat162(h2, h3);
    reinterpret_cast<__nv_bfloat162*>(g_xlo + o)[0] = __halves2bfloat162(l0, l1);
    reinterpret_cast<__nv_bfloat162*>(g_xlo + o)[1] = __halves2bfloat162(l2, l3);
}

// ---------------- nfeats -> bf16 hi/lo (H part, layer 1 only) ----------------
__global__ void k_conv_x0(const float* __restrict__ H) {
    int idx = blockIdx.x * blockDim.x + threadIdx.x;   // NN*32 float4 groups
    if (idx >= NN * 32) return;
    int row = idx >> 5;
    int j   = idx & 31;
    float4 v = reinterpret_cast<const float4*>(H)[(size_t)row * 32 + j];
    __nv_bfloat16 h0 = __float2bfloat16(v.x);
    __nv_bfloat16 h1 = __float2bfloat16(v.y);
    __nv_bfloat16 h2 = __float2bfloat16(v.z);
    __nv_bfloat16 h3 = __float2bfloat16(v.w);
    __nv_bfloat16 l0 = __float2bfloat16(v.x - __bfloat162float(h0));
    __nv_bfloat16 l1 = __float2bfloat16(v.y - __bfloat162float(h1));
    __nv_bfloat16 l2 = __float2bfloat16(v.z - __bfloat162float(h2));
    __nv_bfloat16 l3 = __float2bfloat16(v.w - __bfloat162float(h3));
    size_t o = (size_t)row * 256 + j * 4;
    reinterpret_cast<__nv_bfloat162*>(g_xhi + o)[0] = __halves2bfloat162(h0, h1);
    reinterpret_cast<__nv_bfloat162*>(g_xhi + o)[1] = __halves2bfloat162(h2, h3);
    reinterpret_cast<__nv_bfloat162*>(g_xlo + o)[0] = __halves2bfloat162(l0, l1);
    reinterpret_cast<__nv_bfloat162*>(g_xlo + o)[1] = __halves2bfloat162(l2, l3);
}

__global__ void k_conv_w(const float* __restrict__ W, __nv_bfloat16* __restrict__ hi,
                         __nv_bfloat16* __restrict__ lo) {
    int idx = blockIdx.x * blockDim.x + threadIdx.x;
    if (idx >= 128 * 64) return;
    float4 v = reinterpret_cast<const float4*>(W)[idx];
    __nv_bfloat16 h0 = __float2bfloat16(v.x);
    __nv_bfloat16 h1 = __float2bfloat16(v.y);
    __nv_bfloat16 h2 = __float2bfloat16(v.z);
    __nv_bfloat16 h3 = __float2bfloat16(v.w);
    __nv_bfloat16 l0 = __float2bfloat16(v.x - __bfloat162float(h0));
    __nv_bfloat16 l1 = __float2bfloat16(v.y - __bfloat162float(h1));
    __nv_bfloat16 l2 = __float2bfloat16(v.z - __bfloat162float(h2));
    __nv_bfloat16 l3 = __float2bfloat16(v.w - __bfloat162float(h3));
    size_t o = (size_t)idx * 4;
    reinterpret_cast<__nv_bfloat162*>(hi + o)[0] = __halves2bfloat162(h0, h1);
    reinterpret_cast<__nv_bfloat162*>(hi + o)[1] = __halves2bfloat162(h2, h3);
    reinterpret_cast<__nv_bfloat162*>(lo + o)[0] = __halves2bfloat162(l0, l1);
    reinterpret_cast<__nv_bfloat162*>(lo + o)[1] = __halves2bfloat162(l2, l3);
}

// ---------------- mma.sync bf16-split GEMM ----------------
// out = relu( Xhi*Whi^T + Xlo*Whi^T + Xhi*Wlo^T + b ); optional bf16 hi/lo
// side-write of the output into xh/xl cols 0..127 (next layer's H part).
static constexpr int ROWB    = 144;
static constexpr int TILE_B  = 128 * ROWB;
static constexpr int STAGE_B = 4 * TILE_B;
static constexpr int GSMEM   = 2 * STAGE_B;   // 147456

__global__ __launch_bounds__(256) void k_gemm_mma(const __nv_bfloat16* __restrict__ whi,
                                                  const __nv_bfloat16* __restrict__ wlo,
                                                  const float* __restrict__ bias,
                                                  float* __restrict__ out,
                                                  __nv_bfloat16* __restrict__ xh,
                                                  __nv_bfloat16* __restrict__ xl) {
    extern __shared__ char smem[];
    const uint32_t sb = smem_u32(smem);
    const int tid  = threadIdx.x;
    const int wid  = tid >> 5;
    const int lane = tid & 31;
    const int bm   = blockIdx.x * 128;
    const int wm   = (wid & 3) * 32;
    const int wn   = (wid >> 2) * 64;

    float c[2][8][4];
    #pragma unroll
    for (int i = 0; i < 2; i++)
        #pragma unroll
        for (int j = 0; j < 8; j++)
            #pragma unroll
            for (int k = 0; k < 4; k++) c[i][j][k] = 0.f;

    auto load_chunk = [&](int kb, int st) {
        const uint32_t base = sb + st * STAGE_B;
        #pragma unroll
        for (int j = 0; j < 4; j++) {
            int idx = tid + j * 256;
            int row = idx >> 3;
            int grp = idx & 7;
            uint32_t soff = (uint32_t)(row * ROWB + grp * 16);
            int rg = bm + row;
            if (rg >= NN) rg = NN - 1;
            size_t ga = (size_t)rg * 256 + kb * 64 + grp * 8;
            cp16(base + 0 * TILE_B + soff, g_xhi + ga);
            cp16(base + 1 * TILE_B + soff, g_xlo + ga);
            size_t gw = (size_t)row * 256 + kb * 64 + grp * 8;
            cp16(base + 2 * TILE_B + soff, whi + gw);
            cp16(base + 3 * TILE_B + soff, wlo + gw);
        }
        cp_commit();
    };

    load_chunk(0, 0);

    const int g  = lane >> 3;
    const int l7 = lane & 7;

    #pragma unroll
    for (int kb = 0; kb < 4; kb++) {
        const int st = kb & 1;
        if (kb < 3) {
            load_chunk(kb + 1, st ^ 1);
            cp_wait<1>();
        } else {
            cp_wait<0>();
        }
        __syncthreads();

        const uint32_t baseA = sb + st * STAGE_B;
        const uint32_t baseB = baseA + 2 * TILE_B;

        #pragma unroll
        for (int ks = 0; ks < 4; ks++) {
            const int k0 = ks * 16;
            uint32_t ahi[2][4], alo[2][4], bhi[8][2], blo[8][2];

            #pragma unroll
            for (int mi = 0; mi < 2; mi++) {
                int row = wm + mi * 16 + (g & 1) * 8 + l7;
                uint32_t kbyte = (uint32_t)((k0 + (g >> 1) * 8) * 2);
                uint32_t off = (uint32_t)(row * ROWB) + kbyte;
                ldsm_x4(ahi[mi][0], ahi[mi][1], ahi[mi][2], ahi[mi][3], baseA + off);
                ldsm_x4(alo[mi][0], alo[mi][1], alo[mi][2], alo[mi][3], baseA + TILE_B + off);
            }
            #pragma unroll
            for (int j2 = 0; j2 < 4; j2++) {
                int row = wn + j2 * 16 + (g >> 1) * 8 + l7;
                uint32_t kbyte = (uint32_t)((k0 + (g & 1) * 8) * 2);
                uint32_t off = (uint32_t)(row * ROWB) + kbyte;
                uint32_t r0, r1, r2, r3;
                ldsm_x4(r0, r1, r2, r3, baseB + off);
                bhi[2 * j2][0] = r0; bhi[2 * j2][1] = r1;
                bhi[2 * j2 + 1][0] = r2; bhi[2 * j2 + 1][1] = r3;
                ldsm_x4(r0, r1, r2, r3, baseB + TILE_B + off);
                blo[2 * j2][0] = r0; blo[2 * j2][1] = r1;
                blo[2 * j2 + 1][0] = r2; blo[2 * j2 + 1][1] = r3;
            }

            #pragma unroll
            for (int mi = 0; mi < 2; mi++)
                #pragma unroll
                for (int nj = 0; nj < 8; nj++) {
                    mma16816(c[mi][nj], ahi[mi], bhi[nj]);
                    mma16816(c[mi][nj], alo[mi], bhi[nj]);
                    mma16816(c[mi][nj], ahi[mi], blo[nj]);
                }
        }
        __syncthreads();
    }

    #pragma unroll
    for (int mi = 0; mi < 2; mi++) {
        int m0 = bm + wm + mi * 16 + (lane >> 2);
        #pragma unroll
        for (int r = 0; r < 2; r++) {
            int m = m0 + 8 * r;
            if (m < NN) {
                #pragma unroll
                for (int nj = 0; nj < 8; nj++) {
                    int n = wn + nj * 8 + (lane & 3) * 2;
                    float2 bv = *reinterpret_cast<const float2*>(bias + n);
                    float2 o;
                    o.x = fmaxf(c[mi][nj][2 * r + 0] + bv.x, 0.f);
                    o.y = fmaxf(c[mi][nj][2 * r + 1] + bv.y, 0.f);
                    *reinterpret_cast<float2*>(out + (size_t)m * DD + n) = o;
                    if (xh) {
                        __nv_bfloat16 hx = __float2bfloat16(o.x);
                        __nv_bfloat16 hy = __float2bfloat16(o.y);
                        __nv_bfloat16 lx = __float2bfloat16(o.x - __bfloat162float(hx));
                        __nv_bfloat16 ly = __float2bfloat16(o.y - __bfloat162float(hy));
                        size_t xo = (size_t)m * 256 + n;
                        *reinterpret_cast<__nv_bfloat162*>(xh + xo) = __halves2bfloat162(hx, hy);
                        *reinterpret_cast<__nv_bfloat162*>(xl + xo) = __halves2bfloat162(lx, ly);
                    }
                }
            }
        }
    }
}

// ---------------- launch ----------------
extern "C" void kernel_launch(void* const* d_in, const int* in_sizes, int n_in,
                              void* d_out, int out_size) {
    const float* nfeats = (const float*)d_in[0];
    const float* efeats = (const float*)d_in[1];
    const float* Ww0    = (const float*)d_in[2];
    const float* Wb0    = (const float*)d_in[3];
    const float* aw0    = (const float*)d_in[4];
    const float* ab0    = (const float*)d_in[5];
    const float* Ww1    = (const float*)d_in[6];
    const float* Wb1    = (const float*)d_in[7];
    const float* aw1    = (const float*)d_in[8];
    const float* ab1    = (const float*)d_in[9];
    const int*   src    = (const int*)d_in[10];
    const int*   dst    = (const int*)d_in[11];
    float* out = (float*)d_out;

    float* h1 = nullptr;
    cudaGetSymbolAddress((void**)&h1, g_h1);
    __nv_bfloat16 *whi0, *wlo0, *whi1, *wlo1, *xhi, *xlo;
    cudaGetSymbolAddress((void**)&whi0, g_whi0);
    cudaGetSymbolAddress((void**)&wlo0, g_wlo0);
    cudaGetSymbolAddress((void**)&whi1, g_whi1);
    cudaGetSymbolAddress((void**)&wlo1, g_wlo1);
    cudaGetSymbolAddress((void**)&xhi,  g_xhi);
    cudaGetSymbolAddress((void**)&xlo,  g_xlo);

    static bool init_done = false;
    static cudaStream_t s1 = nullptr;
    static cudaEvent_t ev0 = nullptr, ev1 = nullptr;
    if (!init_done) {
        cudaFuncSetAttribute(k_gemm_mma, cudaFuncAttributeMaxDynamicSharedMemorySize, GSMEM);
        cudaStreamCreateWithFlags(&s1, cudaStreamNonBlocking);
        cudaEventCreateWithFlags(&ev0, cudaEventDisableTiming);
        cudaEventCreateWithFlags(&ev1, cudaEventDisableTiming);
        init_done = true;
    }

    const int E4B = (NE / 4 + 255) / 256;     // 625
    const int EB  = (NE + 255) / 256;         // 2500
    const int NB  = (NN + 255) / 256;
    const int WB  = (NN + 7) / 8;             // 6250
    const int GB  = (NN + 127) / 128;         // 391
    const int CX0 = (NN * 32 + 255) / 256;    // 6250
    const int CWB = (128 * 64 + 255) / 256;   // 32

    // fork: side stream does conversions + layer-1 node dots while the
    // main stream builds the CSR.
    cudaEventRecord(ev0, 0);
    cudaStreamWaitEvent(s1, ev0, 0);

    // main stream: CSR of incoming edges (shared by both layers)
    k_zero_cnt<<<NB, 256>>>();
    k_count4<<<E4B, 256>>>(dst);
    k_scan<<<1, 1024>>>();
    k_fill4<<<E4B, 256>>>(dst);

    // side stream: independent prep
    k_conv_w<<<CWB, 256, 0, s1>>>(Ww0, whi0, wlo0);
    k_conv_w<<<CWB, 256, 0, s1>>>(Ww1, whi1, wlo1);
    k_conv_x0<<<CX0, 256, 0, s1>>>(nfeats);
    k_node_dots<<<WB, 256, 0, s1>>>(nfeats, aw0);

    cudaEventRecord(ev1, s1);
    cudaStreamWaitEvent(0, ev1, 0);

    // layer 1
    k_elog<<<EB, 256>>>(src, dst, ab0);
    k_softmax_z<<<WB, 256>>>(efeats);
    k_gemm_mma<<<GB, 256, GSMEM>>>(whi0, wlo0, Wb0, h1, xhi, xlo);

    // layer 2
    k_node_dots<<<WB, 256>>>(h1, aw1);
    k_elog<<<EB, 256>>>(src, dst, ab1);
    k_softmax_z<<<WB, 256>>>(efeats);
    k_gemm_mma<<<GB, 256, GSMEM>>>(whi1, wlo1, Wb1, out, nullptr, nullptr);
}

// round 6
// speedup vs baseline: 1.4846x; 1.0797x over previous
#include <cuda_runtime.h>
#include <cuda_bf16.h>
#include <cstdint>

#define NN 50000
#define NE 640000
#define DD 128

// ---------------- device scratch ----------------
__device__ float g_ssrc[NN];
__device__ float g_sdst[NN];
__device__ float g_elog[NE];
__device__ int   g_cnt[NN];
__device__ int   g_cur[NN];
__device__ int   g_rowstart[NN + 1];
__device__ int   g_csr[NE];
__device__ int   g_srcs[NE];    // CSR-ordered src node ids
// bf16-split GEMM operands: [N, 256] rows = [H(0:128) | Z(128:256)]
__device__ __nv_bfloat16 g_xhi[(size_t)NN * 256];
__device__ __nv_bfloat16 g_xlo[(size_t)NN * 256];
__device__ __nv_bfloat16 g_whi0[128 * 256];
__device__ __nv_bfloat16 g_wlo0[128 * 256];
__device__ __nv_bfloat16 g_whi1[128 * 256];
__device__ __nv_bfloat16 g_wlo1[128 * 256];

// ---------------- helpers ----------------
__device__ __forceinline__ uint32_t smem_u32(const void* p) {
    uint32_t a;
    asm("{ .reg .u64 t; cvta.to.shared.u64 t, %1; cvt.u32.u64 %0, t; }" : "=r"(a) : "l"(p));
    return a;
}
__device__ __forceinline__ void cp16(uint32_t sdst, const void* gsrc) {
    asm volatile("cp.async.cg.shared.global [%0], [%1], 16;" :: "r"(sdst), "l"(gsrc));
}
__device__ __forceinline__ void cp_commit() {
    asm volatile("cp.async.commit_group;" ::: "memory");
}
template <int N>
__device__ __forceinline__ void cp_wait() {
    asm volatile("cp.async.wait_group %0;" :: "n"(N) : "memory");
}
__device__ __forceinline__ void ldsm_x4(uint32_t& r0, uint32_t& r1, uint32_t& r2, uint32_t& r3,
                                        uint32_t addr) {
    asm volatile("ldmatrix.sync.aligned.m8n8.x4.shared.b16 {%0,%1,%2,%3}, [%4];"
                 : "=r"(r0), "=r"(r1), "=r"(r2), "=r"(r3) : "r"(addr));
}
__device__ __forceinline__ void mma16816(float* c, const uint32_t* a, const uint32_t* b) {
    asm volatile(
        "mma.sync.aligned.m16n8k16.row.col.f32.bf16.bf16.f32 "
        "{%0,%1,%2,%3}, {%4,%5,%6,%7}, {%8,%9}, {%0,%1,%2,%3};"
        : "+f"(c[0]), "+f"(c[1]), "+f"(c[2]), "+f"(c[3])
        : "r"(a[0]), "r"(a[1]), "r"(a[2]), "r"(a[3]), "r"(b[0]), "r"(b[1]));
}

// ---------------- CSR build ----------------
__global__ void k_count4(const int* __restrict__ dst) {
    int i = blockIdx.x * blockDim.x + threadIdx.x;
    if (i < NE / 4) {
        int4 d = reinterpret_cast<const int4*>(dst)[i];
        atomicAdd(&g_cnt[d.x], 1);
        atomicAdd(&g_cnt[d.y], 1);
        atomicAdd(&g_cnt[d.z], 1);
        atomicAdd(&g_cnt[d.w], 1);
    }
}
__global__ void k_scan() {
    __shared__ int sp[1024];
    const int t = threadIdx.x;
    const int C = (NN + 1023) / 1024;
    int base = t * C;
    int s = 0;
    for (int i = 0; i < C; i++) {
        int idx = base + i;
        if (idx < NN) s += g_cnt[idx];
    }
    sp[t] = s;
    __syncthreads();
    for (int off = 1; off < 1024; off <<= 1) {
        int v = (t >= off) ? sp[t - off] : 0;
        __syncthreads();
        sp[t] += v;
        __syncthreads();
    }
    int run = sp[t] - s;
    for (int i = 0; i < C; i++) {
        int idx = base + i;
        if (idx < NN) {
            int c = g_cnt[idx];
            g_rowstart[idx] = run;
            g_cur[idx] = run;
            run += c;
        }
    }
    if (t == 1023) g_rowstart[NN] = run;
}
__global__ void k_fill4(const int* __restrict__ dst, const int* __restrict__ src) {
    int i = blockIdx.x * blockDim.x + threadIdx.x;
    if (i < NE / 4) {
        int4 d = reinterpret_cast<const int4*>(dst)[i];
        int4 s = reinterpret_cast<const int4*>(src)[i];
        int e = i * 4;
        int p0 = atomicAdd(&g_cur[d.x], 1);
        int p1 = atomicAdd(&g_cur[d.y], 1);
        int p2 = atomicAdd(&g_cur[d.z], 1);
        int p3 = atomicAdd(&g_cur[d.w], 1);
        g_csr[p0] = e;     g_srcs[p0] = s.x;
        g_csr[p1] = e + 1; g_srcs[p1] = s.y;
        g_csr[p2] = e + 2; g_srcs[p2] = s.z;
        g_csr[p3] = e + 3; g_srcs[p3] = s.w;
    }
}

// ---------------- per-node partial attention dots (layer 1 only) ----------------
__global__ void k_node_dots(const float* __restrict__ H, const float* __restrict__ AW) {
    int gw   = (blockIdx.x * blockDim.x + threadIdx.x) >> 5;
    int lane = threadIdx.x & 31;
    if (gw >= NN) return;
    float4 hv = reinterpret_cast<const float4*>(H)[(size_t)gw * 32 + lane];
    float4 wl = reinterpret_cast<const float4*>(AW)[lane];
    float4 wh = reinterpret_cast<const float4*>(AW)[lane + 32];
    float ps = hv.x * wl.x + hv.y * wl.y + hv.z * wl.z + hv.w * wl.w;
    float pd = hv.x * wh.x + hv.y * wh.y + hv.z * wh.z + hv.w * wh.w;
    #pragma unroll
    for (int o = 16; o; o >>= 1) {
        ps += __shfl_xor_sync(0xffffffffu, ps, o);
        pd += __shfl_xor_sync(0xffffffffu, pd, o);
    }
    if (lane == 0) { g_ssrc[gw] = ps; g_sdst[gw] = pd; }
}

// ---------------- fused segment softmax + weighted gather ----------------
// warp per node. pass 1: ex = exp(relu(logit)) + denom (no max subtract —
// relu-logits are bounded, analytically identical). pass 2: z accumulation,
// 4 gathers in flight. Writes z as bf16 hi/lo into xhi/xlo cols 128..255.
__global__ void k_softmax_z(const float* __restrict__ efeats,
                            const float* __restrict__ attn_b) {
    int n    = (blockIdx.x * blockDim.x + threadIdx.x) >> 5;
    int lane = threadIdx.x & 31;
    if (n >= NN) return;
    const int beg = g_rowstart[n];
    const int end = g_rowstart[n + 1];
    const float sd = g_sdst[n];
    const float ab = __ldg(attn_b);

    float den = 0.f;
    for (int j = beg + lane; j < end; j += 32) {
        float ev = g_ssrc[g_srcs[j]] + sd + ab;
        ev = ev > 0.f ? ev : 0.f;
        float ex = __expf(ev);
        g_elog[j] = ex;
        den += ex;
    }
    #pragma unroll
    for (int o = 16; o; o >>= 1) den += __shfl_xor_sync(0xffffffffu, den, o);
    float invden = (end > beg) ? (1.0f / den) : 0.f;
    __syncwarp();

    float4 a0 = make_float4(0.f, 0.f, 0.f, 0.f);
    float4 a1 = make_float4(0.f, 0.f, 0.f, 0.f);
    float4 a2 = make_float4(0.f, 0.f, 0.f, 0.f);
    float4 a3 = make_float4(0.f, 0.f, 0.f, 0.f);
    int j = beg;
    for (; j + 4 <= end; j += 4) {
        float w0 = g_elog[j]     * invden;
        float w1 = g_elog[j + 1] * invden;
        float w2 = g_elog[j + 2] * invden;
        float w3 = g_elog[j + 3] * invden;
        int e0 = g_csr[j];
        int e1 = g_csr[j + 1];
        int e2 = g_csr[j + 2];
        int e3 = g_csr[j + 3];
        float4 f0 = reinterpret_cast<const float4*>(efeats)[(size_t)e0 * 32 + lane];
        float4 f1 = reinterpret_cast<const float4*>(efeats)[(size_t)e1 * 32 + lane];
        float4 f2 = reinterpret_cast<const float4*>(efeats)[(size_t)e2 * 32 + lane];
        float4 f3 = reinterpret_cast<const float4*>(efeats)[(size_t)e3 * 32 + lane];
        a0.x = fmaf(w0, f0.x, a0.x); a0.y = fmaf(w0, f0.y, a0.y);
        a0.z = fmaf(w0, f0.z, a0.z); a0.w = fmaf(w0, f0.w, a0.w);
        a1.x = fmaf(w1, f1.x, a1.x); a1.y = fmaf(w1, f1.y, a1.y);
        a1.z = fmaf(w1, f1.z, a1.z); a1.w = fmaf(w1, f1.w, a1.w);
        a2.x = fmaf(w2, f2.x, a2.x); a2.y = fmaf(w2, f2.y, a2.y);
        a2.z = fmaf(w2, f2.z, a2.z); a2.w = fmaf(w2, f2.w, a2.w);
        a3.x = fmaf(w3, f3.x, a3.x); a3.y = fmaf(w3, f3.y, a3.y);
        a3.z = fmaf(w3, f3.z, a3.z); a3.w = fmaf(w3, f3.w, a3.w);
    }
    for (; j < end; j++) {
        float w0 = g_elog[j] * invden;
        int e0 = g_csr[j];
        float4 f0 = reinterpret_cast<const float4*>(efeats)[(size_t)e0 * 32 + lane];
        a0.x = fmaf(w0, f0.x, a0.x); a0.y = fmaf(w0, f0.y, a0.y);
        a0.z = fmaf(w0, f0.z, a0.z); a0.w = fmaf(w0, f0.w, a0.w);
    }
    a0.x += a1.x + a2.x + a3.x;
    a0.y += a1.y + a2.y + a3.y;
    a0.z += a1.z + a2.z + a3.z;
    a0.w += a1.w + a2.w + a3.w;

    __nv_bfloat16 h0 = __float2bfloat16(a0.x);
    __nv_bfloat16 h1 = __float2bfloat16(a0.y);
    __nv_bfloat16 h2 = __float2bfloat16(a0.z);
    __nv_bfloat16 h3 = __float2bfloat16(a0.w);
    __nv_bfloat16 l0 = __float2bfloat16(a0.x - __bfloat162float(h0));
    __nv_bfloat16 l1 = __float2bfloat16(a0.y - __bfloat162float(h1));
    __nv_bfloat16 l2 = __float2bfloat16(a0.z - __bfloat162float(h2));
    __nv_bfloat16 l3 = __float2bfloat16(a0.w - __bfloat162float(h3));
    size_t o = (size_t)n * 256 + 128 + lane * 4;
    reinterpret_cast<__nv_bfloat162*>(g_xhi + o)[0] = __halves2bfloat162(h0, h1);
    reinterpret_cast<__nv_bfloat162*>(g_xhi + o)[1] = __halves2bfloat162(h2, h3);
    reinterpret_cast<__nv_bfloat162*>(g_xlo + o)[0] = __halves2bfloat162(l0, l1);
    reinterpret_cast<__nv_bfloat162*>(g_xlo + o)[1] = __halves2bfloat162(l2, l3);
}

// ---------------- nfeats -> bf16 hi/lo (H part, layer 1 only) ----------------
__global__ void k_conv_x0(const float* __restrict__ H) {
    int idx = blockIdx.x * blockDim.x + threadIdx.x;
    if (idx >= NN * 32) return;
    int row = idx >> 5;
    int j   = idx & 31;
    float4 v = reinterpret_cast<const float4*>(H)[(size_t)row * 32 + j];
    __nv_bfloat16 h0 = __float2bfloat16(v.x);
    __nv_bfloat16 h1 = __float2bfloat16(v.y);
    __nv_bfloat16 h2 = __float2bfloat16(v.z);
    __nv_bfloat16 h3 = __float2bfloat16(v.w);
    __nv_bfloat16 l0 = __float2bfloat16(v.x - __bfloat162float(h0));
    __nv_bfloat16 l1 = __float2bfloat16(v.y - __bfloat162float(h1));
    __nv_bfloat16 l2 = __float2bfloat16(v.z - __bfloat162float(h2));
    __nv_bfloat16 l3 = __float2bfloat16(v.w - __bfloat162float(h3));
    size_t o = (size_t)row * 256 + j * 4;
    reinterpret_cast<__nv_bfloat162*>(g_xhi + o)[0] = __halves2bfloat162(h0, h1);
    reinterpret_cast<__nv_bfloat162*>(g_xhi + o)[1] = __halves2bfloat162(h2, h3);
    reinterpret_cast<__nv_bfloat162*>(g_xlo + o)[0] = __halves2bfloat162(l0, l1);
    reinterpret_cast<__nv_bfloat162*>(g_xlo + o)[1] = __halves2bfloat162(l2, l3);
}

__global__ void k_conv_w(const float* __restrict__ W, __nv_bfloat16* __restrict__ hi,
                         __nv_bfloat16* __restrict__ lo) {
    int idx = blockIdx.x * blockDim.x + threadIdx.x;
    if (idx >= 128 * 64) return;
    float4 v = reinterpret_cast<const float4*>(W)[idx];
    __nv_bfloat16 h0 = __float2bfloat16(v.x);
    __nv_bfloat16 h1 = __float2bfloat16(v.y);
    __nv_bfloat16 h2 = __float2bfloat16(v.z);
    __nv_bfloat16 h3 = __float2bfloat16(v.w);
    __nv_bfloat16 l0 = __float2bfloat16(v.x - __bfloat162float(h0));
    __nv_bfloat16 l1 = __float2bfloat16(v.y - __bfloat162float(h1));
    __nv_bfloat16 l2 = __float2bfloat16(v.z - __bfloat162float(h2));
    __nv_bfloat16 l3 = __float2bfloat16(v.w - __bfloat162float(h3));
    size_t o = (size_t)idx * 4;
    reinterpret_cast<__nv_bfloat162*>(hi + o)[0] = __halves2bfloat162(h0, h1);
    reinterpret_cast<__nv_bfloat162*>(hi + o)[1] = __halves2bfloat162(h2, h3);
    reinterpret_cast<__nv_bfloat162*>(lo + o)[0] = __halves2bfloat162(l0, l1);
    reinterpret_cast<__nv_bfloat162*>(lo + o)[1] = __halves2bfloat162(l2, l3);
}

// ---------------- mma.sync bf16-split GEMM ----------------
// relu( Xhi*Whi^T + Xlo*Whi^T + Xhi*Wlo^T + b ).
// Optional outputs: fp32 `out`, bf16 hi/lo side-write (next layer's H), and
// fused next-layer attention dots (awn != null) via quad-shfl + smem reduce.
static constexpr int ROWB    = 144;
static constexpr int TILE_B  = 128 * ROWB;
static constexpr int STAGE_B = 4 * TILE_B;
static constexpr int GSMEM   = 2 * STAGE_B;   // 147456

__global__ __launch_bounds__(256) void k_gemm_mma(const __nv_bfloat16* __restrict__ whi,
                                                  const __nv_bfloat16* __restrict__ wlo,
                                                  const float* __restrict__ bias,
                                                  float* __restrict__ out,
                                                  __nv_bfloat16* __restrict__ xh,
                                                  __nv_bfloat16* __restrict__ xl,
                                                  const float* __restrict__ awn) {
    extern __shared__ char smem[];
    __shared__ float sdot[2][128][2];
    const uint32_t sb = smem_u32(smem);
    const int tid  = threadIdx.x;
    const int wid  = tid >> 5;
    const int lane = tid & 31;
    const int bm   = blockIdx.x * 128;
    const int wm   = (wid & 3) * 32;
    const int wn   = (wid >> 2) * 64;

    float c[2][8][4];
    #pragma unroll
    for (int i = 0; i < 2; i++)
        #pragma unroll
        for (int j = 0; j < 8; j++)
            #pragma unroll
            for (int k = 0; k < 4; k++) c[i][j][k] = 0.f;

    auto load_chunk = [&](int kb, int st) {
        const uint32_t base = sb + st * STAGE_B;
        #pragma unroll
        for (int j = 0; j < 4; j++) {
            int idx = tid + j * 256;
            int row = idx >> 3;
            int grp = idx & 7;
            uint32_t soff = (uint32_t)(row * ROWB + grp * 16);
            int rg = bm + row;
            if (rg >= NN) rg = NN - 1;
            size_t ga = (size_t)rg * 256 + kb * 64 + grp * 8;
            cp16(base + 0 * TILE_B + soff, g_xhi + ga);
            cp16(base + 1 * TILE_B + soff, g_xlo + ga);
            size_t gw = (size_t)row * 256 + kb * 64 + grp * 8;
            cp16(base + 2 * TILE_B + soff, whi + gw);
            cp16(base + 3 * TILE_B + soff, wlo + gw);
        }
        cp_commit();
    };

    load_chunk(0, 0);

    const int g  = lane >> 3;
    const int l7 = lane & 7;

    #pragma unroll
    for (int kb = 0; kb < 4; kb++) {
        const int st = kb & 1;
        if (kb < 3) {
            load_chunk(kb + 1, st ^ 1);
            cp_wait<1>();
        } else {
            cp_wait<0>();
        }
        __syncthreads();

        const uint32_t baseA = sb + st * STAGE_B;
        const uint32_t baseB = baseA + 2 * TILE_B;

        #pragma unroll
        for (int ks = 0; ks < 4; ks++) {
            const int k0 = ks * 16;
            uint32_t ahi[2][4], alo[2][4], bhi[8][2], blo[8][2];

            #pragma unroll
            for (int mi = 0; mi < 2; mi++) {
                int row = wm + mi * 16 + (g & 1) * 8 + l7;
                uint32_t kbyte = (uint32_t)((k0 + (g >> 1) * 8) * 2);
                uint32_t off = (uint32_t)(row * ROWB) + kbyte;
                ldsm_x4(ahi[mi][0], ahi[mi][1], ahi[mi][2], ahi[mi][3], baseA + off);
                ldsm_x4(alo[mi][0], alo[mi][1], alo[mi][2], alo[mi][3], baseA + TILE_B + off);
            }
            #pragma unroll
            for (int j2 = 0; j2 < 4; j2++) {
                int row = wn + j2 * 16 + (g >> 1) * 8 + l7;
                uint32_t kbyte = (uint32_t)((k0 + (g & 1) * 8) * 2);
                uint32_t off = (uint32_t)(row * ROWB) + kbyte;
                uint32_t r0, r1, r2, r3;
                ldsm_x4(r0, r1, r2, r3, baseB + off);
                bhi[2 * j2][0] = r0; bhi[2 * j2][1] = r1;
                bhi[2 * j2 + 1][0] = r2; bhi[2 * j2 + 1][1] = r3;
                ldsm_x4(r0, r1, r2, r3, baseB + TILE_B + off);
                blo[2 * j2][0] = r0; blo[2 * j2][1] = r1;
                blo[2 * j2 + 1][0] = r2; blo[2 * j2 + 1][1] = r3;
            }

            #pragma unroll
            for (int mi = 0; mi < 2; mi++)
                #pragma unroll
                for (int nj = 0; nj < 8; nj++) {
                    mma16816(c[mi][nj], ahi[mi], bhi[nj]);
                    mma16816(c[mi][nj], alo[mi], bhi[nj]);
                    mma16816(c[mi][nj], ahi[mi], blo[nj]);
                }
        }
        __syncthreads();
    }

    // epilogue
    #pragma unroll
    for (int mi = 0; mi < 2; mi++) {
        #pragma unroll
        for (int r = 0; r < 2; r++) {
            int mloc = wm + mi * 16 + (lane >> 2) + 8 * r;
            int m = bm + mloc;
            float ps = 0.f, pd = 0.f;
            #pragma unroll
            for (int nj = 0; nj < 8; nj++) {
                int n = wn + nj * 8 + (lane & 3) * 2;
                float2 bv = *reinterpret_cast<const float2*>(bias + n);
                float ox = fmaxf(c[mi][nj][2 * r + 0] + bv.x, 0.f);
                float oy = fmaxf(c[mi][nj][2 * r + 1] + bv.y, 0.f);
                if (m < NN) {
                    if (out)
                        *reinterpret_cast<float2*>(out + (size_t)m * DD + n) =
                            make_float2(ox, oy);
                    if (xh) {
                        __nv_bfloat16 hx = __float2bfloat16(ox);
                        __nv_bfloat16 hy = __float2bfloat16(oy);
                        __nv_bfloat16 lx = __float2bfloat16(ox - __bfloat162float(hx));
                        __nv_bfloat16 ly = __float2bfloat16(oy - __bfloat162float(hy));
                        size_t xo = (size_t)m * 256 + n;
                        *reinterpret_cast<__nv_bfloat162*>(xh + xo) = __halves2bfloat162(hx, hy);
                        *reinterpret_cast<__nv_bfloat162*>(xl + xo) = __halves2bfloat162(lx, ly);
                    }
                }
                if (awn) {
                    float2 as = *reinterpret_cast<const float2*>(awn + n);
                    float2 ad = *reinterpret_cast<const float2*>(awn + 128 + n);
                    ps += ox * as.x + oy * as.y;
                    pd += ox * ad.x + oy * ad.y;
                }
            }
            if (awn) {
                ps += __shfl_xor_sync(0xffffffffu, ps, 1);
                ps += __shfl_xor_sync(0xffffffffu, ps, 2);
                pd += __shfl_xor_sync(0xffffffffu, pd, 1);
                pd += __shfl_xor_sync(0xffffffffu, pd, 2);
                if ((lane & 3) == 0) {
                    sdot[wid >> 2][mloc][0] = ps;
                    sdot[wid >> 2][mloc][1] = pd;
                }
            }
        }
    }
    if (awn) {
        __syncthreads();
        if (tid < 128) {
            int m = bm + tid;
            if (m < NN) {
                g_ssrc[m] = sdot[0][tid][0] + sdot[1][tid][0];
                g_sdst[m] = sdot[0][tid][1] + sdot[1][tid][1];
            }
        }
    }
}

// ---------------- launch ----------------
extern "C" void kernel_launch(void* const* d_in, const int* in_sizes, int n_in,
                              void* d_out, int out_size) {
    const float* nfeats = (const float*)d_in[0];
    const float* efeats = (const float*)d_in[1];
    const float* Ww0    = (const float*)d_in[2];
    const float* Wb0    = (const float*)d_in[3];
    const float* aw0    = (const float*)d_in[4];
    const float* ab0    = (const float*)d_in[5];
    const float* Ww1    = (const float*)d_in[6];
    const float* Wb1    = (const float*)d_in[7];
    const float* aw1    = (const float*)d_in[8];
    const float* ab1    = (const float*)d_in[9];
    const int*   src    = (const int*)d_in[10];
    const int*   dst    = (const int*)d_in[11];
    float* out = (float*)d_out;

    __nv_bfloat16 *whi0, *wlo0, *whi1, *wlo1, *xhi, *xlo;
    int* cntp = nullptr;
    cudaGetSymbolAddress((void**)&whi0, g_whi0);
    cudaGetSymbolAddress((void**)&wlo0, g_wlo0);
    cudaGetSymbolAddress((void**)&whi1, g_whi1);
    cudaGetSymbolAddress((void**)&wlo1, g_wlo1);
    cudaGetSymbolAddress((void**)&xhi,  g_xhi);
    cudaGetSymbolAddress((void**)&xlo,  g_xlo);
    cudaGetSymbolAddress((void**)&cntp, g_cnt);

    static bool init_done = false;
    static cudaStream_t s1 = nullptr;
    static cudaEvent_t ev0 = nullptr, ev1 = nullptr;
    if (!init_done) {
        cudaFuncSetAttribute(k_gemm_mma, cudaFuncAttributeMaxDynamicSharedMemorySize, GSMEM);
        cudaStreamCreateWithFlags(&s1, cudaStreamNonBlocking);
        cudaEventCreateWithFlags(&ev0, cudaEventDisableTiming);
        cudaEventCreateWithFlags(&ev1, cudaEventDisableTiming);
        init_done = true;
    }

    const int E4B = (NE / 4 + 255) / 256;     // 625
    const int WB  = (NN + 7) / 8;             // 6250
    const int GB  = (NN + 127) / 128;         // 391
    const int CX0 = (NN * 32 + 255) / 256;    // 6250
    const int CWB = (128 * 64 + 255) / 256;   // 32

    // fork side stream for independent prep while main builds the CSR
    cudaEventRecord(ev0, 0);
    cudaStreamWaitEvent(s1, ev0, 0);

    // main: CSR of incoming edges (shared by both layers)
    cudaMemsetAsync(cntp, 0, NN * sizeof(int), 0);
    k_count4<<<E4B, 256>>>(dst);
    k_scan<<<1, 1024>>>();
    k_fill4<<<E4B, 256>>>(dst, src);

    // side: conversions + layer-1 node dots
    k_conv_w<<<CWB, 256, 0, s1>>>(Ww0, whi0, wlo0);
    k_conv_w<<<CWB, 256, 0, s1>>>(Ww1, whi1, wlo1);
    k_conv_x0<<<CX0, 256, 0, s1>>>(nfeats);
    k_node_dots<<<WB, 256, 0, s1>>>(nfeats, aw0);

    cudaEventRecord(ev1, s1);
    cudaStreamWaitEvent(0, ev1, 0);

    // layer 1: softmax+z, then GEMM (bf16 side-write + fused layer-2 dots,
    // no fp32 output needed)
    k_softmax_z<<<WB, 256>>>(efeats, ab0);
    k_gemm_mma<<<GB, 256, GSMEM>>>(whi0, wlo0, Wb0, nullptr, xhi, xlo, aw1);

    // layer 2
    k_softmax_z<<<WB, 256>>>(efeats, ab1);
    k_gemm_mma<<<GB, 256, GSMEM>>>(whi1, wlo1, Wb1, out, nullptr, nullptr, nullptr);
}

// round 7
// speedup vs baseline: 1.7776x; 1.1973x over previous
#include <cuda_runtime.h>
#include <cuda_bf16.h>
#include <cstdint>

#define NN 50000
#define NE 640000
#define DD 128
#define CAP 64          // padded-CSR capacity per node (max degree ~30)

// ---------------- device scratch ----------------
__device__ float g_ssrc[NN];
__device__ float g_sdst[NN];
__device__ int   g_cnt[NN];
__device__ int   g_csr[(size_t)NN * CAP];    // edge ids, grouped by dst
__device__ int   g_srcs[(size_t)NN * CAP];   // matching src node ids
// bf16-split GEMM operands: [N, 256] rows = [H(0:128) | Z(128:256)]
__device__ __nv_bfloat16 g_xhi[(size_t)NN * 256];
__device__ __nv_bfloat16 g_xlo[(size_t)NN * 256];
__device__ __nv_bfloat16 g_whi0[128 * 256];
__device__ __nv_bfloat16 g_wlo0[128 * 256];
__device__ __nv_bfloat16 g_whi1[128 * 256];
__device__ __nv_bfloat16 g_wlo1[128 * 256];

// ---------------- helpers ----------------
__device__ __forceinline__ uint32_t smem_u32(const void* p) {
    uint32_t a;
    asm("{ .reg .u64 t; cvta.to.shared.u64 t, %1; cvt.u32.u64 %0, t; }" : "=r"(a) : "l"(p));
    return a;
}
__device__ __forceinline__ void cp16(uint32_t sdst, const void* gsrc) {
    asm volatile("cp.async.cg.shared.global [%0], [%1], 16;" :: "r"(sdst), "l"(gsrc));
}
__device__ __forceinline__ void cp_commit() {
    asm volatile("cp.async.commit_group;" ::: "memory");
}
template <int N>
__device__ __forceinline__ void cp_wait() {
    asm volatile("cp.async.wait_group %0;" :: "n"(N) : "memory");
}
__device__ __forceinline__ void ldsm_x4(uint32_t& r0, uint32_t& r1, uint32_t& r2, uint32_t& r3,
                                        uint32_t addr) {
    asm volatile("ldmatrix.sync.aligned.m8n8.x4.shared.b16 {%0,%1,%2,%3}, [%4];"
                 : "=r"(r0), "=r"(r1), "=r"(r2), "=r"(r3) : "r"(addr));
}
__device__ __forceinline__ void mma16816(float* c, const uint32_t* a, const uint32_t* b) {
    asm volatile(
        "mma.sync.aligned.m16n8k16.row.col.f32.bf16.bf16.f32 "
        "{%0,%1,%2,%3}, {%4,%5,%6,%7}, {%8,%9}, {%0,%1,%2,%3};"
        : "+f"(c[0]), "+f"(c[1]), "+f"(c[2]), "+f"(c[3])
        : "r"(a[0]), "r"(a[1]), "r"(a[2]), "r"(a[3]), "r"(b[0]), "r"(b[1]));
}

// ---------------- one-pass padded-CSR build ----------------
__global__ void k_build(const int* __restrict__ dst, const int* __restrict__ src) {
    int i = blockIdx.x * blockDim.x + threadIdx.x;
    if (i < NE / 4) {
        int4 d = reinterpret_cast<const int4*>(dst)[i];
        int4 s = reinterpret_cast<const int4*>(src)[i];
        int e = i * 4;
        int p0 = atomicAdd(&g_cnt[d.x], 1);
        int p1 = atomicAdd(&g_cnt[d.y], 1);
        int p2 = atomicAdd(&g_cnt[d.z], 1);
        int p3 = atomicAdd(&g_cnt[d.w], 1);
        g_csr[(size_t)d.x * CAP + p0] = e;     g_srcs[(size_t)d.x * CAP + p0] = s.x;
        g_csr[(size_t)d.y * CAP + p1] = e + 1; g_srcs[(size_t)d.y * CAP + p1] = s.y;
        g_csr[(size_t)d.z * CAP + p2] = e + 2; g_srcs[(size_t)d.z * CAP + p2] = s.z;
        g_csr[(size_t)d.w * CAP + p3] = e + 3; g_srcs[(size_t)d.w * CAP + p3] = s.w;
    }
}

// ---------------- per-node partial attention dots (layer 1 only) ----------------
__global__ void k_node_dots(const float* __restrict__ H, const float* __restrict__ AW) {
    int gw   = (blockIdx.x * blockDim.x + threadIdx.x) >> 5;
    int lane = threadIdx.x & 31;
    if (gw >= NN) return;
    float4 hv = reinterpret_cast<const float4*>(H)[(size_t)gw * 32 + lane];
    float4 wl = reinterpret_cast<const float4*>(AW)[lane];
    float4 wh = reinterpret_cast<const float4*>(AW)[lane + 32];
    float ps = hv.x * wl.x + hv.y * wl.y + hv.z * wl.z + hv.w * wl.w;
    float pd = hv.x * wh.x + hv.y * wh.y + hv.z * wh.z + hv.w * wh.w;
    #pragma unroll
    for (int o = 16; o; o >>= 1) {
        ps += __shfl_xor_sync(0xffffffffu, ps, o);
        pd += __shfl_xor_sync(0xffffffffu, pd, o);
    }
    if (lane == 0) { g_ssrc[gw] = ps; g_sdst[gw] = pd; }
}

// ---------------- single-pass segment softmax + weighted gather ----------------
// z_n = (sum_e exp(relu(logit_e)) * f_e) / (sum_e exp(relu(logit_e)))
// Unnormalized accumulation: den is lane-uniform (no shuffles at all).
// Writes z as bf16 hi/lo into xhi/xlo cols 128..255.
__global__ void k_softmax_z(const float* __restrict__ efeats,
                            const float* __restrict__ attn_b) {
    int n    = (blockIdx.x * blockDim.x + threadIdx.x) >> 5;
    int lane = threadIdx.x & 31;
    if (n >= NN) return;
    const int cnt = g_cnt[n];
    const int base = n * CAP;
    const float sb = g_sdst[n] + __ldg(attn_b);

    float den = 0.f;
    float4 a0 = make_float4(0.f, 0.f, 0.f, 0.f);
    float4 a1 = make_float4(0.f, 0.f, 0.f, 0.f);
    float4 a2 = make_float4(0.f, 0.f, 0.f, 0.f);
    float4 a3 = make_float4(0.f, 0.f, 0.f, 0.f);

    int j = 0;
    for (; j + 4 <= cnt; j += 4) {
        int4 e4 = *reinterpret_cast<const int4*>(g_csr + base + j);
        int4 s4 = *reinterpret_cast<const int4*>(g_srcs + base + j);
        float w0 = __expf(fmaxf(g_ssrc[s4.x] + sb, 0.f));
        float w1 = __expf(fmaxf(g_ssrc[s4.y] + sb, 0.f));
        float w2 = __expf(fmaxf(g_ssrc[s4.z] + sb, 0.f));
        float w3 = __expf(fmaxf(g_ssrc[s4.w] + sb, 0.f));
        den += (w0 + w1) + (w2 + w3);
        float4 f0 = reinterpret_cast<const float4*>(efeats)[(size_t)e4.x * 32 + lane];
        float4 f1 = reinterpret_cast<const float4*>(efeats)[(size_t)e4.y * 32 + lane];
        float4 f2 = reinterpret_cast<const float4*>(efeats)[(size_t)e4.z * 32 + lane];
        float4 f3 = reinterpret_cast<const float4*>(efeats)[(size_t)e4.w * 32 + lane];
        a0.x = fmaf(w0, f0.x, a0.x); a0.y = fmaf(w0, f0.y, a0.y);
        a0.z = fmaf(w0, f0.z, a0.z); a0.w = fmaf(w0, f0.w, a0.w);
        a1.x = fmaf(w1, f1.x, a1.x); a1.y = fmaf(w1, f1.y, a1.y);
        a1.z = fmaf(w1, f1.z, a1.z); a1.w = fmaf(w1, f1.w, a1.w);
        a2.x = fmaf(w2, f2.x, a2.x); a2.y = fmaf(w2, f2.y, a2.y);
        a2.z = fmaf(w2, f2.z, a2.z); a2.w = fmaf(w2, f2.w, a2.w);
        a3.x = fmaf(w3, f3.x, a3.x); a3.y = fmaf(w3, f3.y, a3.y);
        a3.z = fmaf(w3, f3.z, a3.z); a3.w = fmaf(w3, f3.w, a3.w);
    }
    for (; j < cnt; j++) {
        int e0 = g_csr[base + j];
        int s0 = g_srcs[base + j];
        float w0 = __expf(fmaxf(g_ssrc[s0] + sb, 0.f));
        den += w0;
        float4 f0 = reinterpret_cast<const float4*>(efeats)[(size_t)e0 * 32 + lane];
        a0.x = fmaf(w0, f0.x, a0.x); a0.y = fmaf(w0, f0.y, a0.y);
        a0.z = fmaf(w0, f0.z, a0.z); a0.w = fmaf(w0, f0.w, a0.w);
    }
    a0.x += (a1.x + a2.x) + a3.x;
    a0.y += (a1.y + a2.y) + a3.y;
    a0.z += (a1.z + a2.z) + a3.z;
    a0.w += (a1.w + a2.w) + a3.w;

    float inv = (cnt > 0) ? (1.0f / den) : 0.f;
    a0.x *= inv; a0.y *= inv; a0.z *= inv; a0.w *= inv;

    __nv_bfloat16 h0 = __float2bfloat16(a0.x);
    __nv_bfloat16 h1 = __float2bfloat16(a0.y);
    __nv_bfloat16 h2 = __float2bfloat16(a0.z);
    __nv_bfloat16 h3 = __float2bfloat16(a0.w);
    __nv_bfloat16 l0 = __float2bfloat16(a0.x - __bfloat162float(h0));
    __nv_bfloat16 l1 = __float2bfloat16(a0.y - __bfloat162float(h1));
    __nv_bfloat16 l2 = __float2bfloat16(a0.z - __bfloat162float(h2));
    __nv_bfloat16 l3 = __float2bfloat16(a0.w - __bfloat162float(h3));
    size_t o = (size_t)n * 256 + 128 + lane * 4;
    reinterpret_cast<__nv_bfloat162*>(g_xhi + o)[0] = __halves2bfloat162(h0, h1);
    reinterpret_cast<__nv_bfloat162*>(g_xhi + o)[1] = __halves2bfloat162(h2, h3);
    reinterpret_cast<__nv_bfloat162*>(g_xlo + o)[0] = __halves2bfloat162(l0, l1);
    reinterpret_cast<__nv_bfloat162*>(g_xlo + o)[1] = __halves2bfloat162(l2, l3);
}

// ---------------- nfeats -> bf16 hi/lo (H part, layer 1 only) ----------------
__global__ void k_conv_x0(const float* __restrict__ H) {
    int idx = blockIdx.x * blockDim.x + threadIdx.x;
    if (idx >= NN * 32) return;
    int row = idx >> 5;
    int j   = idx & 31;
    float4 v = reinterpret_cast<const float4*>(H)[(size_t)row * 32 + j];
    __nv_bfloat16 h0 = __float2bfloat16(v.x);
    __nv_bfloat16 h1 = __float2bfloat16(v.y);
    __nv_bfloat16 h2 = __float2bfloat16(v.z);
    __nv_bfloat16 h3 = __float2bfloat16(v.w);
    __nv_bfloat16 l0 = __float2bfloat16(v.x - __bfloat162float(h0));
    __nv_bfloat16 l1 = __float2bfloat16(v.y - __bfloat162float(h1));
    __nv_bfloat16 l2 = __float2bfloat16(v.z - __bfloat162float(h2));
    __nv_bfloat16 l3 = __float2bfloat16(v.w - __bfloat162float(h3));
    size_t o = (size_t)row * 256 + j * 4;
    reinterpret_cast<__nv_bfloat162*>(g_xhi + o)[0] = __halves2bfloat162(h0, h1);
    reinterpret_cast<__nv_bfloat162*>(g_xhi + o)[1] = __halves2bfloat162(h2, h3);
    reinterpret_cast<__nv_bfloat162*>(g_xlo + o)[0] = __halves2bfloat162(l0, l1);
    reinterpret_cast<__nv_bfloat162*>(g_xlo + o)[1] = __halves2bfloat162(l2, l3);
}

__global__ void k_conv_w(const float* __restrict__ W, __nv_bfloat16* __restrict__ hi,
                         __nv_bfloat16* __restrict__ lo) {
    int idx = blockIdx.x * blockDim.x + threadIdx.x;
    if (idx >= 128 * 64) return;
    float4 v = reinterpret_cast<const float4*>(W)[idx];
    __nv_bfloat16 h0 = __float2bfloat16(v.x);
    __nv_bfloat16 h1 = __float2bfloat16(v.y);
    __nv_bfloat16 h2 = __float2bfloat16(v.z);
    __nv_bfloat16 h3 = __float2bfloat16(v.w);
    __nv_bfloat16 l0 = __float2bfloat16(v.x - __bfloat162float(h0));
    __nv_bfloat16 l1 = __float2bfloat16(v.y - __bfloat162float(h1));
    __nv_bfloat16 l2 = __float2bfloat16(v.z - __bfloat162float(h2));
    __nv_bfloat16 l3 = __float2bfloat16(v.w - __bfloat162float(h3));
    size_t o = (size_t)idx * 4;
    reinterpret_cast<__nv_bfloat162*>(hi + o)[0] = __halves2bfloat162(h0, h1);
    reinterpret_cast<__nv_bfloat162*>(hi + o)[1] = __halves2bfloat162(h2, h3);
    reinterpret_cast<__nv_bfloat162*>(lo + o)[0] = __halves2bfloat162(l0, l1);
    reinterpret_cast<__nv_bfloat162*>(lo + o)[1] = __halves2bfloat162(l2, l3);
}

// ---------------- mma.sync bf16-split GEMM ----------------
static constexpr int ROWB    = 144;
static constexpr int TILE_B  = 128 * ROWB;
static constexpr int STAGE_B = 4 * TILE_B;
static constexpr int GSMEM   = 2 * STAGE_B;   // 147456

__global__ __launch_bounds__(256) void k_gemm_mma(const __nv_bfloat16* __restrict__ whi,
                                                  const __nv_bfloat16* __restrict__ wlo,
                                                  const float* __restrict__ bias,
                                                  float* __restrict__ out,
                                                  __nv_bfloat16* __restrict__ xh,
                                                  __nv_bfloat16* __restrict__ xl,
                                                  const float* __restrict__ awn) {
    extern __shared__ char smem[];
    __shared__ float sdot[2][128][2];
    const uint32_t sb = smem_u32(smem);
    const int tid  = threadIdx.x;
    const int wid  = tid >> 5;
    const int lane = tid & 31;
    const int bm   = blockIdx.x * 128;
    const int wm   = (wid & 3) * 32;
    const int wn   = (wid >> 2) * 64;

    float c[2][8][4];
    #pragma unroll
    for (int i = 0; i < 2; i++)
        #pragma unroll
        for (int j = 0; j < 8; j++)
            #pragma unroll
            for (int k = 0; k < 4; k++) c[i][j][k] = 0.f;

    auto load_chunk = [&](int kb, int st) {
        const uint32_t base = sb + st * STAGE_B;
        #pragma unroll
        for (int j = 0; j < 4; j++) {
            int idx = tid + j * 256;
            int row = idx >> 3;
            int grp = idx & 7;
            uint32_t soff = (uint32_t)(row * ROWB + grp * 16);
            int rg = bm + row;
            if (rg >= NN) rg = NN - 1;
            size_t ga = (size_t)rg * 256 + kb * 64 + grp * 8;
            cp16(base + 0 * TILE_B + soff, g_xhi + ga);
            cp16(base + 1 * TILE_B + soff, g_xlo + ga);
            size_t gw = (size_t)row * 256 + kb * 64 + grp * 8;
            cp16(base + 2 * TILE_B + soff, whi + gw);
            cp16(base + 3 * TILE_B + soff, wlo + gw);
        }
        cp_commit();
    };

    load_chunk(0, 0);

    const int g  = lane >> 3;
    const int l7 = lane & 7;

    #pragma unroll
    for (int kb = 0; kb < 4; kb++) {
        const int st = kb & 1;
        if (kb < 3) {
            load_chunk(kb + 1, st ^ 1);
            cp_wait<1>();
        } else {
            cp_wait<0>();
        }
        __syncthreads();

        const uint32_t baseA = sb + st * STAGE_B;
        const uint32_t baseB = baseA + 2 * TILE_B;

        #pragma unroll
        for (int ks = 0; ks < 4; ks++) {
            const int k0 = ks * 16;
            uint32_t ahi[2][4], alo[2][4], bhi[8][2], blo[8][2];

            #pragma unroll
            for (int mi = 0; mi < 2; mi++) {
                int row = wm + mi * 16 + (g & 1) * 8 + l7;
                uint32_t kbyte = (uint32_t)((k0 + (g >> 1) * 8) * 2);
                uint32_t off = (uint32_t)(row * ROWB) + kbyte;
                ldsm_x4(ahi[mi][0], ahi[mi][1], ahi[mi][2], ahi[mi][3], baseA + off);
                ldsm_x4(alo[mi][0], alo[mi][1], alo[mi][2], alo[mi][3], baseA + TILE_B + off);
            }
            #pragma unroll
            for (int j2 = 0; j2 < 4; j2++) {
                int row = wn + j2 * 16 + (g >> 1) * 8 + l7;
                uint32_t kbyte = (uint32_t)((k0 + (g & 1) * 8) * 2);
                uint32_t off = (uint32_t)(row * ROWB) + kbyte;
                uint32_t r0, r1, r2, r3;
                ldsm_x4(r0, r1, r2, r3, baseB + off);
                bhi[2 * j2][0] = r0; bhi[2 * j2][1] = r1;
                bhi[2 * j2 + 1][0] = r2; bhi[2 * j2 + 1][1] = r3;
                ldsm_x4(r0, r1, r2, r3, baseB + TILE_B + off);
                blo[2 * j2][0] = r0; blo[2 * j2][1] = r1;
                blo[2 * j2 + 1][0] = r2; blo[2 * j2 + 1][1] = r3;
            }

            #pragma unroll
            for (int mi = 0; mi < 2; mi++)
                #pragma unroll
                for (int nj = 0; nj < 8; nj++) {
                    mma16816(c[mi][nj], ahi[mi], bhi[nj]);
                    mma16816(c[mi][nj], alo[mi], bhi[nj]);
                    mma16816(c[mi][nj], ahi[mi], blo[nj]);
                }
        }
        __syncthreads();
    }

    // epilogue
    #pragma unroll
    for (int mi = 0; mi < 2; mi++) {
        #pragma unroll
        for (int r = 0; r < 2; r++) {
            int mloc = wm + mi * 16 + (lane >> 2) + 8 * r;
            int m = bm + mloc;
            float ps = 0.f, pd = 0.f;
            #pragma unroll
            for (int nj = 0; nj < 8; nj++) {
                int n = wn + nj * 8 + (lane & 3) * 2;
                float2 bv = *reinterpret_cast<const float2*>(bias + n);
                float ox = fmaxf(c[mi][nj][2 * r + 0] + bv.x, 0.f);
                float oy = fmaxf(c[mi][nj][2 * r + 1] + bv.y, 0.f);
                if (m < NN) {
                    if (out)
                        *reinterpret_cast<float2*>(out + (size_t)m * DD + n) =
                            make_float2(ox, oy);
                    if (xh) {
                        __nv_bfloat16 hx = __float2bfloat16(ox);
                        __nv_bfloat16 hy = __float2bfloat16(oy);
                        __nv_bfloat16 lx = __float2bfloat16(ox - __bfloat162float(hx));
                        __nv_bfloat16 ly = __float2bfloat16(oy - __bfloat162float(hy));
                        size_t xo = (size_t)m * 256 + n;
                        *reinterpret_cast<__nv_bfloat162*>(xh + xo) = __halves2bfloat162(hx, hy);
                        *reinterpret_cast<__nv_bfloat162*>(xl + xo) = __halves2bfloat162(lx, ly);
                    }
                }
                if (awn) {
                    float2 as = *reinterpret_cast<const float2*>(awn + n);
                    float2 ad = *reinterpret_cast<const float2*>(awn + 128 + n);
                    ps += ox * as.x + oy * as.y;
                    pd += ox * ad.x + oy * ad.y;
                }
            }
            if (awn) {
                ps += __shfl_xor_sync(0xffffffffu, ps, 1);
                ps += __shfl_xor_sync(0xffffffffu, ps, 2);
                pd += __shfl_xor_sync(0xffffffffu, pd, 1);
                pd += __shfl_xor_sync(0xffffffffu, pd, 2);
                if ((lane & 3) == 0) {
                    sdot[wid >> 2][mloc][0] = ps;
                    sdot[wid >> 2][mloc][1] = pd;
                }
            }
        }
    }
    if (awn) {
        __syncthreads();
        if (tid < 128) {
            int m = bm + tid;
            if (m < NN) {
                g_ssrc[m] = sdot[0][tid][0] + sdot[1][tid][0];
                g_sdst[m] = sdot[0][tid][1] + sdot[1][tid][1];
            }
        }
    }
}

// ---------------- launch ----------------
extern "C" void kernel_launch(void* const* d_in, const int* in_sizes, int n_in,
                              void* d_out, int out_size) {
    const float* nfeats = (const float*)d_in[0];
    const float* efeats = (const float*)d_in[1];
    const float* Ww0    = (const float*)d_in[2];
    const float* Wb0    = (const float*)d_in[3];
    const float* aw0    = (const float*)d_in[4];
    const float* ab0    = (const float*)d_in[5];
    const float* Ww1    = (const float*)d_in[6];
    const float* Wb1    = (const float*)d_in[7];
    const float* aw1    = (const float*)d_in[8];
    const float* ab1    = (const float*)d_in[9];
    const int*   src    = (const int*)d_in[10];
    const int*   dst    = (const int*)d_in[11];
    float* out = (float*)d_out;

    __nv_bfloat16 *whi0, *wlo0, *whi1, *wlo1, *xhi, *xlo;
    int* cntp = nullptr;
    cudaGetSymbolAddress((void**)&whi0, g_whi0);
    cudaGetSymbolAddress((void**)&wlo0, g_wlo0);
    cudaGetSymbolAddress((void**)&whi1, g_whi1);
    cudaGetSymbolAddress((void**)&wlo1, g_wlo1);
    cudaGetSymbolAddress((void**)&xhi,  g_xhi);
    cudaGetSymbolAddress((void**)&xlo,  g_xlo);
    cudaGetSymbolAddress((void**)&cntp, g_cnt);

    static bool init_done = false;
    static cudaStream_t s1 = nullptr;
    static cudaEvent_t ev0 = nullptr, ev1 = nullptr;
    if (!init_done) {
        cudaFuncSetAttribute(k_gemm_mma, cudaFuncAttributeMaxDynamicSharedMemorySize, GSMEM);
        cudaStreamCreateWithFlags(&s1, cudaStreamNonBlocking);
        cudaEventCreateWithFlags(&ev0, cudaEventDisableTiming);
        cudaEventCreateWithFlags(&ev1, cudaEventDisableTiming);
        init_done = true;
    }

    const int E4B = (NE / 4 + 255) / 256;     // 625
    const int WB  = (NN + 7) / 8;             // 6250
    const int GB  = (NN + 127) / 128;         // 391
    const int CX0 = (NN * 32 + 255) / 256;    // 6250
    const int CWB = (128 * 64 + 255) / 256;   // 32

    // fork side stream for independent prep while main builds the CSR
    cudaEventRecord(ev0, 0);
    cudaStreamWaitEvent(s1, ev0, 0);

    // main: one-pass padded CSR (shared by both layers)
    cudaMemsetAsync(cntp, 0, NN * sizeof(int), 0);
    k_build<<<E4B, 256>>>(dst, src);

    // side: conversions + layer-1 node dots
    k_conv_w<<<CWB, 256, 0, s1>>>(Ww0, whi0, wlo0);
    k_conv_w<<<CWB, 256, 0, s1>>>(Ww1, whi1, wlo1);
    k_conv_x0<<<CX0, 256, 0, s1>>>(nfeats);
    k_node_dots<<<WB, 256, 0, s1>>>(nfeats, aw0);

    cudaEventRecord(ev1, s1);
    cudaStreamWaitEvent(0, ev1, 0);

    // layer 1: single-pass softmax+z, then GEMM (bf16 side-write + fused
    // layer-2 dots, no fp32 output needed)
    k_softmax_z<<<WB, 256>>>(efeats, ab0);
    k_gemm_mma<<<GB, 256, GSMEM>>>(whi0, wlo0, Wb0, nullptr, xhi, xlo, aw1);

    // layer 2
    k_softmax_z<<<WB, 256>>>(efeats, ab1);
    k_gemm_mma<<<GB, 256, GSMEM>>>(whi1, wlo1, Wb1, out, nullptr, nullptr, nullptr);
}

// round 8
// speedup vs baseline: 1.8700x; 1.0520x over previous
#include <cuda_runtime.h>
#include <cuda_bf16.h>
#include <cstdint>

#define NN 50000
#define NE 640000
#define DD 128
#define CAP 64          // padded-CSR capacity per node (max degree ~30)

// ---------------- device scratch ----------------
__device__ float g_ssrc[NN];
__device__ float g_sdst[NN];
__device__ int   g_cnt[NN];
__device__ int   g_csr[(size_t)NN * CAP];    // edge ids, grouped by dst
__device__ int   g_srcs[(size_t)NN * CAP];   // matching src node ids
// bf16-split GEMM operands: [N, 256] rows = [H(0:128) | Z(128:256)]
__device__ __nv_bfloat16 g_xhi[(size_t)NN * 256];
__device__ __nv_bfloat16 g_xlo[(size_t)NN * 256];
__device__ __nv_bfloat16 g_whi0[128 * 256];
__device__ __nv_bfloat16 g_wlo0[128 * 256];
__device__ __nv_bfloat16 g_whi1[128 * 256];
__device__ __nv_bfloat16 g_wlo1[128 * 256];

// ---------------- helpers ----------------
__device__ __forceinline__ uint32_t smem_u32(const void* p) {
    uint32_t a;
    asm("{ .reg .u64 t; cvta.to.shared.u64 t, %1; cvt.u32.u64 %0, t; }" : "=r"(a) : "l"(p));
    return a;
}
__device__ __forceinline__ void cp16(uint32_t sdst, const void* gsrc) {
    asm volatile("cp.async.cg.shared.global [%0], [%1], 16;" :: "r"(sdst), "l"(gsrc));
}
__device__ __forceinline__ void cp_commit() {
    asm volatile("cp.async.commit_group;" ::: "memory");
}
template <int N>
__device__ __forceinline__ void cp_wait() {
    asm volatile("cp.async.wait_group %0;" :: "n"(N) : "memory");
}
__device__ __forceinline__ void ldsm_x4(uint32_t& r0, uint32_t& r1, uint32_t& r2, uint32_t& r3,
                                        uint32_t addr) {
    asm volatile("ldmatrix.sync.aligned.m8n8.x4.shared.b16 {%0,%1,%2,%3}, [%4];"
                 : "=r"(r0), "=r"(r1), "=r"(r2), "=r"(r3) : "r"(addr));
}
__device__ __forceinline__ void mma16816(float* c, const uint32_t* a, const uint32_t* b) {
    asm volatile(
        "mma.sync.aligned.m16n8k16.row.col.f32.bf16.bf16.f32 "
        "{%0,%1,%2,%3}, {%4,%5,%6,%7}, {%8,%9}, {%0,%1,%2,%3};"
        : "+f"(c[0]), "+f"(c[1]), "+f"(c[2]), "+f"(c[3])
        : "r"(a[0]), "r"(a[1]), "r"(a[2]), "r"(a[3]), "r"(b[0]), "r"(b[1]));
}
__device__ __forceinline__ void split_store(float x, float y, __nv_bfloat16* hi,
                                            __nv_bfloat16* lo) {
    __nv_bfloat16 hx = __float2bfloat16(x);
    __nv_bfloat16 hy = __float2bfloat16(y);
    __nv_bfloat16 lx = __float2bfloat16(x - __bfloat162float(hx));
    __nv_bfloat16 ly = __float2bfloat16(y - __bfloat162float(hy));
    *reinterpret_cast<__nv_bfloat162*>(hi) = __halves2bfloat162(hx, hy);
    *reinterpret_cast<__nv_bfloat162*>(lo) = __halves2bfloat162(lx, ly);
}

// ---------------- one-pass padded-CSR build ----------------
__global__ void k_build(const int* __restrict__ dst, const int* __restrict__ src) {
    int i = blockIdx.x * blockDim.x + threadIdx.x;
    if (i < NE / 4) {
        int4 d = reinterpret_cast<const int4*>(dst)[i];
        int4 s = reinterpret_cast<const int4*>(src)[i];
        int e = i * 4;
        int p0 = atomicAdd(&g_cnt[d.x], 1);
        int p1 = atomicAdd(&g_cnt[d.y], 1);
        int p2 = atomicAdd(&g_cnt[d.z], 1);
        int p3 = atomicAdd(&g_cnt[d.w], 1);
        g_csr[(size_t)d.x * CAP + p0] = e;     g_srcs[(size_t)d.x * CAP + p0] = s.x;
        g_csr[(size_t)d.y * CAP + p1] = e + 1; g_srcs[(size_t)d.y * CAP + p1] = s.y;
        g_csr[(size_t)d.z * CAP + p2] = e + 2; g_srcs[(size_t)d.z * CAP + p2] = s.z;
        g_csr[(size_t)d.w * CAP + p3] = e + 3; g_srcs[(size_t)d.w * CAP + p3] = s.w;
    }
}

// ---------------- fused: nfeats -> dots + bf16 hi/lo (layer 1 prep) ----------------
__global__ void k_prep(const float* __restrict__ H, const float* __restrict__ AW) {
    int gw   = (blockIdx.x * blockDim.x + threadIdx.x) >> 5;
    int lane = threadIdx.x & 31;
    if (gw >= NN) return;
    float4 hv = reinterpret_cast<const float4*>(H)[(size_t)gw * 32 + lane];
    float4 wl = reinterpret_cast<const float4*>(AW)[lane];
    float4 wh = reinterpret_cast<const float4*>(AW)[lane + 32];
    float ps = hv.x * wl.x + hv.y * wl.y + hv.z * wl.z + hv.w * wl.w;
    float pd = hv.x * wh.x + hv.y * wh.y + hv.z * wh.z + hv.w * wh.w;
    #pragma unroll
    for (int o = 16; o; o >>= 1) {
        ps += __shfl_xor_sync(0xffffffffu, ps, o);
        pd += __shfl_xor_sync(0xffffffffu, pd, o);
    }
    if (lane == 0) { g_ssrc[gw] = ps; g_sdst[gw] = pd; }
    size_t o = (size_t)gw * 256 + lane * 4;
    split_store(hv.x, hv.y, g_xhi + o,     g_xlo + o);
    split_store(hv.z, hv.w, g_xhi + o + 2, g_xlo + o + 2);
}

// ---------------- single-pass segment softmax + weighted gather ----------------
__global__ void k_softmax_z(const float* __restrict__ efeats,
                            const float* __restrict__ attn_b) {
    int n    = (blockIdx.x * blockDim.x + threadIdx.x) >> 5;
    int lane = threadIdx.x & 31;
    if (n >= NN) return;
    const int cnt = g_cnt[n];
    const int base = n * CAP;
    const float sb = g_sdst[n] + __ldg(attn_b);

    float den = 0.f;
    float4 a0 = make_float4(0.f, 0.f, 0.f, 0.f);
    float4 a1 = make_float4(0.f, 0.f, 0.f, 0.f);
    float4 a2 = make_float4(0.f, 0.f, 0.f, 0.f);
    float4 a3 = make_float4(0.f, 0.f, 0.f, 0.f);

    int j = 0;
    for (; j + 4 <= cnt; j += 4) {
        int4 e4 = *reinterpret_cast<const int4*>(g_csr + base + j);
        int4 s4 = *reinterpret_cast<const int4*>(g_srcs + base + j);
        float w0 = __expf(fmaxf(g_ssrc[s4.x] + sb, 0.f));
        float w1 = __expf(fmaxf(g_ssrc[s4.y] + sb, 0.f));
        float w2 = __expf(fmaxf(g_ssrc[s4.z] + sb, 0.f));
        float w3 = __expf(fmaxf(g_ssrc[s4.w] + sb, 0.f));
        den += (w0 + w1) + (w2 + w3);
        float4 f0 = reinterpret_cast<const float4*>(efeats)[(size_t)e4.x * 32 + lane];
        float4 f1 = reinterpret_cast<const float4*>(efeats)[(size_t)e4.y * 32 + lane];
        float4 f2 = reinterpret_cast<const float4*>(efeats)[(size_t)e4.z * 32 + lane];
        float4 f3 = reinterpret_cast<const float4*>(efeats)[(size_t)e4.w * 32 + lane];
        a0.x = fmaf(w0, f0.x, a0.x); a0.y = fmaf(w0, f0.y, a0.y);
        a0.z = fmaf(w0, f0.z, a0.z); a0.w = fmaf(w0, f0.w, a0.w);
        a1.x = fmaf(w1, f1.x, a1.x); a1.y = fmaf(w1, f1.y, a1.y);
        a1.z = fmaf(w1, f1.z, a1.z); a1.w = fmaf(w1, f1.w, a1.w);
        a2.x = fmaf(w2, f2.x, a2.x); a2.y = fmaf(w2, f2.y, a2.y);
        a2.z = fmaf(w2, f2.z, a2.z); a2.w = fmaf(w2, f2.w, a2.w);
        a3.x = fmaf(w3, f3.x, a3.x); a3.y = fmaf(w3, f3.y, a3.y);
        a3.z = fmaf(w3, f3.z, a3.z); a3.w = fmaf(w3, f3.w, a3.w);
    }
    for (; j < cnt; j++) {
        int e0 = g_csr[base + j];
        int s0 = g_srcs[base + j];
        float w0 = __expf(fmaxf(g_ssrc[s0] + sb, 0.f));
        den += w0;
        float4 f0 = reinterpret_cast<const float4*>(efeats)[(size_t)e0 * 32 + lane];
        a0.x = fmaf(w0, f0.x, a0.x); a0.y = fmaf(w0, f0.y, a0.y);
        a0.z = fmaf(w0, f0.z, a0.z); a0.w = fmaf(w0, f0.w, a0.w);
    }
    a0.x += (a1.x + a2.x) + a3.x;
    a0.y += (a1.y + a2.y) + a3.y;
    a0.z += (a1.z + a2.z) + a3.z;
    a0.w += (a1.w + a2.w) + a3.w;

    float inv = (cnt > 0) ? (1.0f / den) : 0.f;
    a0.x *= inv; a0.y *= inv; a0.z *= inv; a0.w *= inv;

    size_t o = (size_t)n * 256 + 128 + lane * 4;
    split_store(a0.x, a0.y, g_xhi + o,     g_xlo + o);
    split_store(a0.z, a0.w, g_xhi + o + 2, g_xlo + o + 2);
}

__global__ void k_conv_w(const float* __restrict__ W, __nv_bfloat16* __restrict__ hi,
                         __nv_bfloat16* __restrict__ lo) {
    int idx = blockIdx.x * blockDim.x + threadIdx.x;
    if (idx >= 128 * 64) return;
    float4 v = reinterpret_cast<const float4*>(W)[idx];
    size_t o = (size_t)idx * 4;
    split_store(v.x, v.y, hi + o,     lo + o);
    split_store(v.z, v.w, hi + o + 2, lo + o + 2);
}

// ---------------- mma.sync bf16-split GEMM ----------------
// BK=32 double-buffered: stage = 4 tiles x (128 rows x 32 bf16, 80B padded rows)
// smem = 2*40960 = 80KB  ->  2 CTAs/SM.
static constexpr int ROWB    = 80;
static constexpr int TILE_B  = 128 * ROWB;    // 10240
static constexpr int STAGE_B = 4 * TILE_B;    // 40960
static constexpr int GSMEM   = 2 * STAGE_B;   // 81920

__global__ __launch_bounds__(256, 2) void k_gemm_mma(const __nv_bfloat16* __restrict__ whi,
                                                     const __nv_bfloat16* __restrict__ wlo,
                                                     const float* __restrict__ bias,
                                                     float* __restrict__ out,
                                                     __nv_bfloat16* __restrict__ xh,
                                                     __nv_bfloat16* __restrict__ xl,
                                                     const float* __restrict__ awn) {
    extern __shared__ char smem[];
    __shared__ float sdot[2][128][2];
    const uint32_t sb = smem_u32(smem);
    const int tid  = threadIdx.x;
    const int wid  = tid >> 5;
    const int lane = tid & 31;
    const int bm   = blockIdx.x * 128;
    const int wm   = (wid & 3) * 32;
    const int wn   = (wid >> 2) * 64;

    float c[2][8][4];
    #pragma unroll
    for (int i = 0; i < 2; i++)
        #pragma unroll
        for (int j = 0; j < 8; j++)
            #pragma unroll
            for (int k = 0; k < 4; k++) c[i][j][k] = 0.f;

    // per stage: 4 tiles x 512 16B-groups / 256 threads = 2 groups per tile
    auto load_chunk = [&](int kb, int st) {
        const uint32_t base = sb + st * STAGE_B;
        #pragma unroll
        for (int j = 0; j < 2; j++) {
            int idx = tid + j * 256;
            int row = idx >> 2;
            int grp = idx & 3;
            uint32_t soff = (uint32_t)(row * ROWB + grp * 16);
            int rg = bm + row;
            if (rg >= NN) rg = NN - 1;
            size_t ga = (size_t)rg * 256 + kb * 32 + grp * 8;
            cp16(base + 0 * TILE_B + soff, g_xhi + ga);
            cp16(base + 1 * TILE_B + soff, g_xlo + ga);
            size_t gw = (size_t)row * 256 + kb * 32 + grp * 8;
            cp16(base + 2 * TILE_B + soff, whi + gw);
            cp16(base + 3 * TILE_B + soff, wlo + gw);
        }
        cp_commit();
    };

    load_chunk(0, 0);

    const int g  = lane >> 3;
    const int l7 = lane & 7;

    #pragma unroll
    for (int kb = 0; kb < 8; kb++) {
        const int st = kb & 1;
        if (kb < 7) {
            load_chunk(kb + 1, st ^ 1);
            cp_wait<1>();
        } else {
            cp_wait<0>();
        }
        __syncthreads();

        const uint32_t baseA = sb + st * STAGE_B;
        const uint32_t baseB = baseA + 2 * TILE_B;

        #pragma unroll
        for (int ks = 0; ks < 2; ks++) {
            const int k0 = ks * 16;
            uint32_t ahi[2][4], alo[2][4];

            #pragma unroll
            for (int mi = 0; mi < 2; mi++) {
                int row = wm + mi * 16 + (g & 1) * 8 + l7;
                uint32_t kbyte = (uint32_t)((k0 + (g >> 1) * 8) * 2);
                uint32_t off = (uint32_t)(row * ROWB) + kbyte;
                ldsm_x4(ahi[mi][0], ahi[mi][1], ahi[mi][2], ahi[mi][3], baseA + off);
                ldsm_x4(alo[mi][0], alo[mi][1], alo[mi][2], alo[mi][3], baseA + TILE_B + off);
            }
            #pragma unroll
            for (int j2 = 0; j2 < 4; j2++) {
                int row = wn + j2 * 16 + (g >> 1) * 8 + l7;
                uint32_t kbyte = (uint32_t)((k0 + (g & 1) * 8) * 2);
                uint32_t off = (uint32_t)(row * ROWB) + kbyte;
                uint32_t bh[4], bl[4];
                ldsm_x4(bh[0], bh[1], bh[2], bh[3], baseB + off);
                ldsm_x4(bl[0], bl[1], bl[2], bl[3], baseB + TILE_B + off);
                #pragma unroll
                for (int mi = 0; mi < 2; mi++) {
                    mma16816(c[mi][2 * j2],     ahi[mi], bh);
                    mma16816(c[mi][2 * j2],     alo[mi], bh);
                    mma16816(c[mi][2 * j2],     ahi[mi], bl);
                    mma16816(c[mi][2 * j2 + 1], ahi[mi], bh + 2);
                    mma16816(c[mi][2 * j2 + 1], alo[mi], bh + 2);
                    mma16816(c[mi][2 * j2 + 1], ahi[mi], bl + 2);
                }
            }
        }
        __syncthreads();
    }

    // epilogue
    #pragma unroll
    for (int mi = 0; mi < 2; mi++) {
        #pragma unroll
        for (int r = 0; r < 2; r++) {
            int mloc = wm + mi * 16 + (lane >> 2) + 8 * r;
            int m = bm + mloc;
            float ps = 0.f, pd = 0.f;
            #pragma unroll
            for (int nj = 0; nj < 8; nj++) {
                int n = wn + nj * 8 + (lane & 3) * 2;
                float2 bv = *reinterpret_cast<const float2*>(bias + n);
                float ox = fmaxf(c[mi][nj][2 * r + 0] + bv.x, 0.f);
                float oy = fmaxf(c[mi][nj][2 * r + 1] + bv.y, 0.f);
                if (m < NN) {
                    if (out)
                        *reinterpret_cast<float2*>(out + (size_t)m * DD + n) =
                            make_float2(ox, oy);
                    if (xh) {
                        size_t xo = (size_t)m * 256 + n;
                        split_store(ox, oy, xh + xo, xl + xo);
                    }
                }
                if (awn) {
                    float2 as = *reinterpret_cast<const float2*>(awn + n);
                    float2 ad = *reinterpret_cast<const float2*>(awn + 128 + n);
                    ps += ox * as.x + oy * as.y;
                    pd += ox * ad.x + oy * ad.y;
                }
            }
            if (awn) {
                ps += __shfl_xor_sync(0xffffffffu, ps, 1);
                ps += __shfl_xor_sync(0xffffffffu, ps, 2);
                pd += __shfl_xor_sync(0xffffffffu, pd, 1);
                pd += __shfl_xor_sync(0xffffffffu, pd, 2);
                if ((lane & 3) == 0) {
                    sdot[wid >> 2][mloc][0] = ps;
                    sdot[wid >> 2][mloc][1] = pd;
                }
            }
        }
    }
    if (awn) {
        __syncthreads();
        if (tid < 128) {
            int m = bm + tid;
            if (m < NN) {
                g_ssrc[m] = sdot[0][tid][0] + sdot[1][tid][0];
                g_sdst[m] = sdot[0][tid][1] + sdot[1][tid][1];
            }
        }
    }
}

// ---------------- launch ----------------
extern "C" void kernel_launch(void* const* d_in, const int* in_sizes, int n_in,
                              void* d_out, int out_size) {
    const float* nfeats = (const float*)d_in[0];
    const float* efeats = (const float*)d_in[1];
    const float* Ww0    = (const float*)d_in[2];
    const float* Wb0    = (const float*)d_in[3];
    const float* aw0    = (const float*)d_in[4];
    const float* ab0    = (const float*)d_in[5];
    const float* Ww1    = (const float*)d_in[6];
    const float* Wb1    = (const float*)d_in[7];
    const float* aw1    = (const float*)d_in[8];
    const float* ab1    = (const float*)d_in[9];
    const int*   src    = (const int*)d_in[10];
    const int*   dst    = (const int*)d_in[11];
    float* out = (float*)d_out;

    __nv_bfloat16 *whi0, *wlo0, *whi1, *wlo1, *xhi, *xlo;
    int* cntp = nullptr;
    cudaGetSymbolAddress((void**)&whi0, g_whi0);
    cudaGetSymbolAddress((void**)&wlo0, g_wlo0);
    cudaGetSymbolAddress((void**)&whi1, g_whi1);
    cudaGetSymbolAddress((void**)&wlo1, g_wlo1);
    cudaGetSymbolAddress((void**)&xhi,  g_xhi);
    cudaGetSymbolAddress((void**)&xlo,  g_xlo);
    cudaGetSymbolAddress((void**)&cntp, g_cnt);

    static bool init_done = false;
    static cudaStream_t s1 = nullptr;
    static cudaEvent_t ev0 = nullptr, evA = nullptr, evB = nullptr;
    if (!init_done) {
        cudaFuncSetAttribute(k_gemm_mma, cudaFuncAttributeMaxDynamicSharedMemorySize, GSMEM);
        cudaStreamCreateWithFlags(&s1, cudaStreamNonBlocking);
        cudaEventCreateWithFlags(&ev0, cudaEventDisableTiming);
        cudaEventCreateWithFlags(&evA, cudaEventDisableTiming);
        cudaEventCreateWithFlags(&evB, cudaEventDisableTiming);
        init_done = true;
    }

    const int E4B = (NE / 4 + 255) / 256;     // 625
    const int WB  = (NN + 7) / 8;             // 6250
    const int GB  = (NN + 127) / 128;         // 391
    const int CWB = (128 * 64 + 255) / 256;   // 32

    // fork side stream
    cudaEventRecord(ev0, 0);
    cudaStreamWaitEvent(s1, ev0, 0);

    // main: one-pass padded CSR (shared by both layers)
    cudaMemsetAsync(cntp, 0, NN * sizeof(int), 0);
    k_build<<<E4B, 256>>>(dst, src);

    // side: fused dots+conv of nfeats (gates softmax1), then weight conversions
    // (gate gemm1 only — they overlap with softmax1)
    k_prep<<<WB, 256, 0, s1>>>(nfeats, aw0);
    cudaEventRecord(evA, s1);
    k_conv_w<<<CWB, 256, 0, s1>>>(Ww0, whi0, wlo0);
    k_conv_w<<<CWB, 256, 0, s1>>>(Ww1, whi1, wlo1);
    cudaEventRecord(evB, s1);

    // layer 1
    cudaStreamWaitEvent(0, evA, 0);
    k_softmax_z<<<WB, 256>>>(efeats, ab0);
    cudaStreamWaitEvent(0, evB, 0);
    k_gemm_mma<<<GB, 256, GSMEM>>>(whi0, wlo0, Wb0, nullptr, xhi, xlo, aw1);

    // layer 2
    k_softmax_z<<<WB, 256>>>(efeats, ab1);
    k_gemm_mma<<<GB, 256, GSMEM>>>(whi1, wlo1, Wb1, out, nullptr, nullptr, nullptr);
}

// round 9
// speedup vs baseline: 2.0104x; 1.0750x over previous
#include <cuda_runtime.h>
#include <cuda_fp16.h>
#include <cstdint>

#define NN 50000
#define NE 640000
#define DD 128
#define CAP 64          // padded-CSR capacity per node (max degree ~30)

// ---------------- device scratch ----------------
__device__ float g_ssrc[NN];
__device__ float g_sdst[NN];
__device__ int   g_cnt[NN];
__device__ int   g_csr[(size_t)NN * CAP];    // edge ids, grouped by dst
__device__ int   g_srcs[(size_t)NN * CAP];   // matching src node ids
// fp16-split GEMM operands: [N, 256] rows = [H(0:128) | Z(128:256)]
__device__ __half g_xhi[(size_t)NN * 256];
__device__ __half g_xlo[(size_t)NN * 256];
__device__ __half g_wh0[128 * 256];
__device__ __half g_wh1[128 * 256];

// ---------------- helpers ----------------
__device__ __forceinline__ uint32_t smem_u32(const void* p) {
    uint32_t a;
    asm("{ .reg .u64 t; cvta.to.shared.u64 t, %1; cvt.u32.u64 %0, t; }" : "=r"(a) : "l"(p));
    return a;
}
__device__ __forceinline__ void cp16(uint32_t sdst, const void* gsrc) {
    asm volatile("cp.async.cg.shared.global [%0], [%1], 16;" :: "r"(sdst), "l"(gsrc));
}
__device__ __forceinline__ void cp_commit() {
    asm volatile("cp.async.commit_group;" ::: "memory");
}
template <int N>
__device__ __forceinline__ void cp_wait() {
    asm volatile("cp.async.wait_group %0;" :: "n"(N) : "memory");
}
__device__ __forceinline__ void ldsm_x4(uint32_t& r0, uint32_t& r1, uint32_t& r2, uint32_t& r3,
                                        uint32_t addr) {
    asm volatile("ldmatrix.sync.aligned.m8n8.x4.shared.b16 {%0,%1,%2,%3}, [%4];"
                 : "=r"(r0), "=r"(r1), "=r"(r2), "=r"(r3) : "r"(addr));
}
__device__ __forceinline__ void mma16816h(float* c, const uint32_t* a, const uint32_t* b) {
    asm volatile(
        "mma.sync.aligned.m16n8k16.row.col.f32.f16.f16.f32 "
        "{%0,%1,%2,%3}, {%4,%5,%6,%7}, {%8,%9}, {%0,%1,%2,%3};"
        : "+f"(c[0]), "+f"(c[1]), "+f"(c[2]), "+f"(c[3])
        : "r"(a[0]), "r"(a[1]), "r"(a[2]), "r"(a[3]), "r"(b[0]), "r"(b[1]));
}
__device__ __forceinline__ void split_store(float x, float y, __half* hi, __half* lo) {
    __half hx = __float2half_rn(x);
    __half hy = __float2half_rn(y);
    __half lx = __float2half_rn(x - __half2float(hx));
    __half ly = __float2half_rn(y - __half2float(hy));
    *reinterpret_cast<__half2*>(hi) = __halves2half2(hx, hy);
    *reinterpret_cast<__half2*>(lo) = __halves2half2(lx, ly);
}

// ---------------- one-pass padded-CSR build ----------------
__global__ void k_build(const int* __restrict__ dst, const int* __restrict__ src) {
    int i = blockIdx.x * blockDim.x + threadIdx.x;
    if (i < NE / 4) {
        int4 d = reinterpret_cast<const int4*>(dst)[i];
        int4 s = reinterpret_cast<const int4*>(src)[i];
        int e = i * 4;
        int p0 = atomicAdd(&g_cnt[d.x], 1);
        int p1 = atomicAdd(&g_cnt[d.y], 1);
        int p2 = atomicAdd(&g_cnt[d.z], 1);
        int p3 = atomicAdd(&g_cnt[d.w], 1);
        g_csr[(size_t)d.x * CAP + p0] = e;     g_srcs[(size_t)d.x * CAP + p0] = s.x;
        g_csr[(size_t)d.y * CAP + p1] = e + 1; g_srcs[(size_t)d.y * CAP + p1] = s.y;
        g_csr[(size_t)d.z * CAP + p2] = e + 2; g_srcs[(size_t)d.z * CAP + p2] = s.z;
        g_csr[(size_t)d.w * CAP + p3] = e + 3; g_srcs[(size_t)d.w * CAP + p3] = s.w;
    }
}

// ---------------- fused: nfeats -> dots + fp16 hi/lo (layer 1 prep) ----------------
__global__ void k_prep(const float* __restrict__ H, const float* __restrict__ AW) {
    int gw   = (blockIdx.x * blockDim.x + threadIdx.x) >> 5;
    int lane = threadIdx.x & 31;
    if (gw >= NN) return;
    float4 hv = reinterpret_cast<const float4*>(H)[(size_t)gw * 32 + lane];
    float4 wl = reinterpret_cast<const float4*>(AW)[lane];
    float4 wh = reinterpret_cast<const float4*>(AW)[lane + 32];
    float ps = hv.x * wl.x + hv.y * wl.y + hv.z * wl.z + hv.w * wl.w;
    float pd = hv.x * wh.x + hv.y * wh.y + hv.z * wh.z + hv.w * wh.w;
    #pragma unroll
    for (int o = 16; o; o >>= 1) {
        ps += __shfl_xor_sync(0xffffffffu, ps, o);
        pd += __shfl_xor_sync(0xffffffffu, pd, o);
    }
    if (lane == 0) { g_ssrc[gw] = ps; g_sdst[gw] = pd; }
    size_t o = (size_t)gw * 256 + lane * 4;
    split_store(hv.x, hv.y, g_xhi + o,     g_xlo + o);
    split_store(hv.z, hv.w, g_xhi + o + 2, g_xlo + o + 2);
}

// ---------------- single-pass segment softmax + weighted gather ----------------
__global__ void k_softmax_z(const float* __restrict__ efeats,
                            const float* __restrict__ attn_b) {
    int n    = (blockIdx.x * blockDim.x + threadIdx.x) >> 5;
    int lane = threadIdx.x & 31;
    if (n >= NN) return;
    const int cnt = g_cnt[n];
    const int base = n * CAP;
    const float sb = g_sdst[n] + __ldg(attn_b);

    float den = 0.f;
    float4 a0 = make_float4(0.f, 0.f, 0.f, 0.f);
    float4 a1 = make_float4(0.f, 0.f, 0.f, 0.f);
    float4 a2 = make_float4(0.f, 0.f, 0.f, 0.f);
    float4 a3 = make_float4(0.f, 0.f, 0.f, 0.f);

    int j = 0;
    for (; j + 4 <= cnt; j += 4) {
        int4 e4 = *reinterpret_cast<const int4*>(g_csr + base + j);
        int4 s4 = *reinterpret_cast<const int4*>(g_srcs + base + j);
        float w0 = __expf(fmaxf(g_ssrc[s4.x] + sb, 0.f));
        float w1 = __expf(fmaxf(g_ssrc[s4.y] + sb, 0.f));
        float w2 = __expf(fmaxf(g_ssrc[s4.z] + sb, 0.f));
        float w3 = __expf(fmaxf(g_ssrc[s4.w] + sb, 0.f));
        den += (w0 + w1) + (w2 + w3);
        float4 f0 = reinterpret_cast<const float4*>(efeats)[(size_t)e4.x * 32 + lane];
        float4 f1 = reinterpret_cast<const float4*>(efeats)[(size_t)e4.y * 32 + lane];
        float4 f2 = reinterpret_cast<const float4*>(efeats)[(size_t)e4.z * 32 + lane];
        float4 f3 = reinterpret_cast<const float4*>(efeats)[(size_t)e4.w * 32 + lane];
        a0.x = fmaf(w0, f0.x, a0.x); a0.y = fmaf(w0, f0.y, a0.y);
        a0.z = fmaf(w0, f0.z, a0.z); a0.w = fmaf(w0, f0.w, a0.w);
        a1.x = fmaf(w1, f1.x, a1.x); a1.y = fmaf(w1, f1.y, a1.y);
        a1.z = fmaf(w1, f1.z, a1.z); a1.w = fmaf(w1, f1.w, a1.w);
        a2.x = fmaf(w2, f2.x, a2.x); a2.y = fmaf(w2, f2.y, a2.y);
        a2.z = fmaf(w2, f2.z, a2.z); a2.w = fmaf(w2, f2.w, a2.w);
        a3.x = fmaf(w3, f3.x, a3.x); a3.y = fmaf(w3, f3.y, a3.y);
        a3.z = fmaf(w3, f3.z, a3.z); a3.w = fmaf(w3, f3.w, a3.w);
    }
    for (; j < cnt; j++) {
        int e0 = g_csr[base + j];
        int s0 = g_srcs[base + j];
        float w0 = __expf(fmaxf(g_ssrc[s0] + sb, 0.f));
        den += w0;
        float4 f0 = reinterpret_cast<const float4*>(efeats)[(size_t)e0 * 32 + lane];
        a0.x = fmaf(w0, f0.x, a0.x); a0.y = fmaf(w0, f0.y, a0.y);
        a0.z = fmaf(w0, f0.z, a0.z); a0.w = fmaf(w0, f0.w, a0.w);
    }
    a0.x += (a1.x + a2.x) + a3.x;
    a0.y += (a1.y + a2.y) + a3.y;
    a0.z += (a1.z + a2.z) + a3.z;
    a0.w += (a1.w + a2.w) + a3.w;

    float inv = (cnt > 0) ? (1.0f / den) : 0.f;
    a0.x *= inv; a0.y *= inv; a0.z *= inv; a0.w *= inv;

    size_t o = (size_t)n * 256 + 128 + lane * 4;
    split_store(a0.x, a0.y, g_xhi + o,     g_xlo + o);
    split_store(a0.z, a0.w, g_xhi + o + 2, g_xlo + o + 2);
}

// ---------------- both weight matrices -> fp16 (single launch) ----------------
__global__ void k_conv_w2(const float* __restrict__ W0, const float* __restrict__ W1) {
    int idx = blockIdx.x * blockDim.x + threadIdx.x;   // 2 x 8192 float4 groups
    if (idx >= 2 * 128 * 64) return;
    const float* W = (idx < 128 * 64) ? W0 : W1;
    __half* out = (idx < 128 * 64) ? g_wh0 : g_wh1;
    int l = idx & (128 * 64 - 1);
    float4 v = reinterpret_cast<const float4*>(W)[l];
    __half2 h01 = __halves2half2(__float2half_rn(v.x), __float2half_rn(v.y));
    __half2 h23 = __halves2half2(__float2half_rn(v.z), __float2half_rn(v.w));
    size_t o = (size_t)l * 4;
    *reinterpret_cast<__half2*>(out + o)     = h01;
    *reinterpret_cast<__half2*>(out + o + 2) = h23;
}

// ---------------- mma.sync fp16 2-term GEMM ----------------
// out = relu( (Xhi + Xlo) * Wh^T + b );  dropped term x*Wlo ~ 7e-5 relative.
// BK=32 double-buffered: stage = 3 tiles x (128 rows x 32 fp16, 80B padded rows)
static constexpr int ROWB    = 80;
static constexpr int TILE_B  = 128 * ROWB;    // 10240
static constexpr int STAGE_B = 3 * TILE_B;    // 30720
static constexpr int GSMEM   = 2 * STAGE_B;   // 61440 -> 2 CTAs/SM

__global__ __launch_bounds__(256, 2) void k_gemm_mma(const __half* __restrict__ wh,
                                                     const float* __restrict__ bias,
                                                     float* __restrict__ out,
                                                     __half* __restrict__ xh,
                                                     __half* __restrict__ xl,
                                                     const float* __restrict__ awn) {
    extern __shared__ char smem[];
    __shared__ float sdot[2][128][2];
    const uint32_t sb = smem_u32(smem);
    const int tid  = threadIdx.x;
    const int wid  = tid >> 5;
    const int lane = tid & 31;
    const int bm   = blockIdx.x * 128;
    const int wm   = (wid & 3) * 32;
    const int wn   = (wid >> 2) * 64;

    float c[2][8][4];
    #pragma unroll
    for (int i = 0; i < 2; i++)
        #pragma unroll
        for (int j = 0; j < 8; j++)
            #pragma unroll
            for (int k = 0; k < 4; k++) c[i][j][k] = 0.f;

    // per stage: 3 tiles x 512 16B-groups / 256 threads = 2 groups per tile
    auto load_chunk = [&](int kb, int st) {
        const uint32_t base = sb + st * STAGE_B;
        #pragma unroll
        for (int j = 0; j < 2; j++) {
            int idx = tid + j * 256;
            int row = idx >> 2;
            int grp = idx & 3;
            uint32_t soff = (uint32_t)(row * ROWB + grp * 16);
            int rg = bm + row;
            if (rg >= NN) rg = NN - 1;
            size_t ga = (size_t)rg * 256 + kb * 32 + grp * 8;
            cp16(base + 0 * TILE_B + soff, g_xhi + ga);
            cp16(base + 1 * TILE_B + soff, g_xlo + ga);
            size_t gw = (size_t)row * 256 + kb * 32 + grp * 8;
            cp16(base + 2 * TILE_B + soff, wh + gw);
        }
        cp_commit();
    };

    load_chunk(0, 0);

    const int g  = lane >> 3;
    const int l7 = lane & 7;

    #pragma unroll
    for (int kb = 0; kb < 8; kb++) {
        const int st = kb & 1;
        if (kb < 7) {
            load_chunk(kb + 1, st ^ 1);
            cp_wait<1>();
        } else {
            cp_wait<0>();
        }
        __syncthreads();

        const uint32_t baseA = sb + st * STAGE_B;
        const uint32_t baseB = baseA + 2 * TILE_B;

        #pragma unroll
        for (int ks = 0; ks < 2; ks++) {
            const int k0 = ks * 16;
            uint32_t ahi[2][4], alo[2][4];

            #pragma unroll
            for (int mi = 0; mi < 2; mi++) {
                int row = wm + mi * 16 + (g & 1) * 8 + l7;
                uint32_t kbyte = (uint32_t)((k0 + (g >> 1) * 8) * 2);
                uint32_t off = (uint32_t)(row * ROWB) + kbyte;
                ldsm_x4(ahi[mi][0], ahi[mi][1], ahi[mi][2], ahi[mi][3], baseA + off);
                ldsm_x4(alo[mi][0], alo[mi][1], alo[mi][2], alo[mi][3], baseA + TILE_B + off);
            }
            #pragma unroll
            for (int j2 = 0; j2 < 4; j2++) {
                int row = wn + j2 * 16 + (g >> 1) * 8 + l7;
                uint32_t kbyte = (uint32_t)((k0 + (g & 1) * 8) * 2);
                uint32_t off = (uint32_t)(row * ROWB) + kbyte;
                uint32_t bh[4];
                ldsm_x4(bh[0], bh[1], bh[2], bh[3], baseB + off);
                #pragma unroll
                for (int mi = 0; mi < 2; mi++) {
                    mma16816h(c[mi][2 * j2],     ahi[mi], bh);
                    mma16816h(c[mi][2 * j2],     alo[mi], bh);
                    mma16816h(c[mi][2 * j2 + 1], ahi[mi], bh + 2);
                    mma16816h(c[mi][2 * j2 + 1], alo[mi], bh + 2);
                }
            }
        }
        __syncthreads();
    }

    // epilogue
    #pragma unroll
    for (int mi = 0; mi < 2; mi++) {
        #pragma unroll
        for (int r = 0; r < 2; r++) {
            int mloc = wm + mi * 16 + (lane >> 2) + 8 * r;
            int m = bm + mloc;
            float ps = 0.f, pd = 0.f;
            #pragma unroll
            for (int nj = 0; nj < 8; nj++) {
                int n = wn + nj * 8 + (lane & 3) * 2;
                float2 bv = *reinterpret_cast<const float2*>(bias + n);
                float ox = fmaxf(c[mi][nj][2 * r + 0] + bv.x, 0.f);
                float oy = fmaxf(c[mi][nj][2 * r + 1] + bv.y, 0.f);
                if (m < NN) {
                    if (out)
                        *reinterpret_cast<float2*>(out + (size_t)m * DD + n) =
                            make_float2(ox, oy);
                    if (xh) {
                        size_t xo = (size_t)m * 256 + n;
                        split_store(ox, oy, xh + xo, xl + xo);
                    }
                }
                if (awn) {
                    float2 as = *reinterpret_cast<const float2*>(awn + n);
                    float2 ad = *reinterpret_cast<const float2*>(awn + 128 + n);
                    ps += ox * as.x + oy * as.y;
                    pd += ox * ad.x + oy * ad.y;
                }
            }
            if (awn) {
                ps += __shfl_xor_sync(0xffffffffu, ps, 1);
                ps += __shfl_xor_sync(0xffffffffu, ps, 2);
                pd += __shfl_xor_sync(0xffffffffu, pd, 1);
                pd += __shfl_xor_sync(0xffffffffu, pd, 2);
                if ((lane & 3) == 0) {
                    sdot[wid >> 2][mloc][0] = ps;
                    sdot[wid >> 2][mloc][1] = pd;
                }
            }
        }
    }
    if (awn) {
        __syncthreads();
        if (tid < 128) {
            int m = bm + tid;
            if (m < NN) {
                g_ssrc[m] = sdot[0][tid][0] + sdot[1][tid][0];
                g_sdst[m] = sdot[0][tid][1] + sdot[1][tid][1];
            }
        }
    }
}

// ---------------- launch ----------------
extern "C" void kernel_launch(void* const* d_in, const int* in_sizes, int n_in,
                              void* d_out, int out_size) {
    const float* nfeats = (const float*)d_in[0];
    const float* efeats = (const float*)d_in[1];
    const float* Ww0    = (const float*)d_in[2];
    const float* Wb0    = (const float*)d_in[3];
    const float* aw0    = (const float*)d_in[4];
    const float* ab0    = (const float*)d_in[5];
    const float* Ww1    = (const float*)d_in[6];
    const float* Wb1    = (const float*)d_in[7];
    const float* aw1    = (const float*)d_in[8];
    const float* ab1    = (const float*)d_in[9];
    const int*   src    = (const int*)d_in[10];
    const int*   dst    = (const int*)d_in[11];
    float* out = (float*)d_out;

    __half *wh0, *wh1, *xhi, *xlo;
    int* cntp = nullptr;
    cudaGetSymbolAddress((void**)&wh0, g_wh0);
    cudaGetSymbolAddress((void**)&wh1, g_wh1);
    cudaGetSymbolAddress((void**)&xhi, g_xhi);
    cudaGetSymbolAddress((void**)&xlo, g_xlo);
    cudaGetSymbolAddress((void**)&cntp, g_cnt);

    static bool init_done = false;
    static cudaStream_t s1 = nullptr;
    static cudaEvent_t ev0 = nullptr, evA = nullptr, evB = nullptr;
    if (!init_done) {
        cudaFuncSetAttribute(k_gemm_mma, cudaFuncAttributeMaxDynamicSharedMemorySize, GSMEM);
        cudaStreamCreateWithFlags(&s1, cudaStreamNonBlocking);
        cudaEventCreateWithFlags(&ev0, cudaEventDisableTiming);
        cudaEventCreateWithFlags(&evA, cudaEventDisableTiming);
        cudaEventCreateWithFlags(&evB, cudaEventDisableTiming);
        init_done = true;
    }

    const int E4B = (NE / 4 + 255) / 256;     // 625
    const int WB  = (NN + 7) / 8;             // 6250
    const int GB  = (NN + 127) / 128;         // 391
    const int CWB = (2 * 128 * 64 + 255) / 256;   // 64

    // fork side stream
    cudaEventRecord(ev0, 0);
    cudaStreamWaitEvent(s1, ev0, 0);

    // main: one-pass padded CSR (shared by both layers)
    cudaMemsetAsync(cntp, 0, NN * sizeof(int), 0);
    k_build<<<E4B, 256>>>(dst, src);

    // side: fused dots+conv of nfeats (gates softmax1), then both weight
    // conversions in one launch (gates gemm1 only)
    k_prep<<<WB, 256, 0, s1>>>(nfeats, aw0);
    cudaEventRecord(evA, s1);
    k_conv_w2<<<CWB, 256, 0, s1>>>(Ww0, Ww1);
    cudaEventRecord(evB, s1);

    // layer 1
    cudaStreamWaitEvent(0, evA, 0);
    k_softmax_z<<<WB, 256>>>(efeats, ab0);
    cudaStreamWaitEvent(0, evB, 0);
    k_gemm_mma<<<GB, 256, GSMEM>>>(wh0, Wb0, nullptr, xhi, xlo, aw1);

    // layer 2
    k_softmax_z<<<WB, 256>>>(efeats, ab1);
    k_gemm_mma<<<GB, 256, GSMEM>>>(wh1, Wb1, out, nullptr, nullptr, nullptr);
}

// round 11
// speedup vs baseline: 2.3927x; 1.1902x over previous
#include <cuda_runtime.h>
#include <cuda_fp16.h>
#include <cstdint>

#define NN 50000
#define NE 640000
#define DD 128
#define CAP 64          // padded-CSR capacity per node (max degree ~30)

// ---------------- device scratch ----------------
__device__ float g_ssrc[NN];
__device__ float g_sdst[NN];
__device__ int   g_cnt[NN];
__device__ int   g_csr[(size_t)NN * CAP];    // edge ids, grouped by dst
__device__ int   g_srcs[(size_t)NN * CAP];   // matching src node ids
// fp16-split GEMM operands: [N, 256] rows = [H(0:128) | Z(128:256)]
__device__ __half g_xhi[(size_t)NN * 256];
__device__ __half g_xlo[(size_t)NN * 256];
__device__ __half g_wh0[128 * 256];
__device__ __half g_wh1[128 * 256];

// ---------------- helpers ----------------
__device__ __forceinline__ uint32_t smem_u32(const void* p) {
    uint32_t a;
    asm("{ .reg .u64 t; cvta.to.shared.u64 t, %1; cvt.u32.u64 %0, t; }" : "=r"(a) : "l"(p));
    return a;
}
__device__ __forceinline__ void cp16(uint32_t sdst, const void* gsrc) {
    asm volatile("cp.async.cg.shared.global [%0], [%1], 16;" :: "r"(sdst), "l"(gsrc));
}
__device__ __forceinline__ void cp_commit() {
    asm volatile("cp.async.commit_group;" ::: "memory");
}
template <int N>
__device__ __forceinline__ void cp_wait() {
    asm volatile("cp.async.wait_group %0;" :: "n"(N) : "memory");
}
__device__ __forceinline__ void ldsm_x4(uint32_t& r0, uint32_t& r1, uint32_t& r2, uint32_t& r3,
                                        uint32_t addr) {
    asm volatile("ldmatrix.sync.aligned.m8n8.x4.shared.b16 {%0,%1,%2,%3}, [%4];"
                 : "=r"(r0), "=r"(r1), "=r"(r2), "=r"(r3) : "r"(addr));
}
__device__ __forceinline__ void mma16816h(float* c, const uint32_t* a, const uint32_t* b) {
    asm volatile(
        "mma.sync.aligned.m16n8k16.row.col.f32.f16.f16.f32 "
        "{%0,%1,%2,%3}, {%4,%5,%6,%7}, {%8,%9}, {%0,%1,%2,%3};"
        : "+f"(c[0]), "+f"(c[1]), "+f"(c[2]), "+f"(c[3])
        : "r"(a[0]), "r"(a[1]), "r"(a[2]), "r"(a[3]), "r"(b[0]), "r"(b[1]));
}
__device__ __forceinline__ void split_store(float x, float y, __half* hi, __half* lo) {
    __half hx = __float2half_rn(x);
    __half hy = __float2half_rn(y);
    __half lx = __float2half_rn(x - __half2float(hx));
    __half ly = __float2half_rn(y - __half2float(hy));
    *reinterpret_cast<__half2*>(hi) = __halves2half2(hx, hy);
    *reinterpret_cast<__half2*>(lo) = __halves2half2(lx, ly);
}

// ---------------- one-pass padded-CSR build ----------------
__global__ void k_build(const int* __restrict__ dst, const int* __restrict__ src) {
    int i = blockIdx.x * blockDim.x + threadIdx.x;
    if (i < NE / 4) {
        int4 d = reinterpret_cast<const int4*>(dst)[i];
        int4 s = reinterpret_cast<const int4*>(src)[i];
        int e = i * 4;
        int p0 = atomicAdd(&g_cnt[d.x], 1);
        int p1 = atomicAdd(&g_cnt[d.y], 1);
        int p2 = atomicAdd(&g_cnt[d.z], 1);
        int p3 = atomicAdd(&g_cnt[d.w], 1);
        g_csr[(size_t)d.x * CAP + p0] = e;     g_srcs[(size_t)d.x * CAP + p0] = s.x;
        g_csr[(size_t)d.y * CAP + p1] = e + 1; g_srcs[(size_t)d.y * CAP + p1] = s.y;
        g_csr[(size_t)d.z * CAP + p2] = e + 2; g_srcs[(size_t)d.z * CAP + p2] = s.z;
        g_csr[(size_t)d.w * CAP + p3] = e + 3; g_srcs[(size_t)d.w * CAP + p3] = s.w;
    }
}

// ---------------- fused: nfeats -> dots + fp16 hi/lo (layer 1 prep) ----------------
__global__ void k_prep(const float* __restrict__ H, const float* __restrict__ AW) {
    int gw   = (blockIdx.x * blockDim.x + threadIdx.x) >> 5;
    int lane = threadIdx.x & 31;
    if (gw >= NN) return;
    float4 hv = reinterpret_cast<const float4*>(H)[(size_t)gw * 32 + lane];
    float4 wl = reinterpret_cast<const float4*>(AW)[lane];
    float4 wh = reinterpret_cast<const float4*>(AW)[lane + 32];
    float ps = hv.x * wl.x + hv.y * wl.y + hv.z * wl.z + hv.w * wl.w;
    float pd = hv.x * wh.x + hv.y * wh.y + hv.z * wh.z + hv.w * wh.w;
    #pragma unroll
    for (int o = 16; o; o >>= 1) {
        ps += __shfl_xor_sync(0xffffffffu, ps, o);
        pd += __shfl_xor_sync(0xffffffffu, pd, o);
    }
    if (lane == 0) { g_ssrc[gw] = ps; g_sdst[gw] = pd; }
    size_t o = (size_t)gw * 256 + lane * 4;
    split_store(hv.x, hv.y, g_xhi + o,     g_xlo + o);
    split_store(hv.z, hv.w, g_xhi + o + 2, g_xlo + o + 2);
}

// ---------------- single-pass segment softmax + weighted gather ----------------
// Phase A: lane-parallel weights (one exp chain per lane, not per edge),
//          stored to per-warp smem; butterfly reduce for den.
// Phase B: pure gather+FMA, streaming loads, weights broadcast from smem.
__global__ __launch_bounds__(256, 6) void k_softmax_z(const float* __restrict__ efeats,
                                                      const float* __restrict__ attn_b) {
    __shared__ float sw[8][CAP];
    int n    = (blockIdx.x * blockDim.x + threadIdx.x) >> 5;
    int ws   = threadIdx.x >> 5;
    int lane = threadIdx.x & 31;
    if (n >= NN) return;
    const int cnt = g_cnt[n];
    const int base = n * CAP;
    const float sb = g_sdst[n] + __ldg(attn_b);

    // phase A: weights in parallel across lanes
    float den = 0.f;
    for (int j = lane; j < cnt; j += 32) {
        int s0 = g_srcs[base + j];
        float w = __expf(fmaxf(g_ssrc[s0] + sb, 0.f));
        sw[ws][j] = w;
        den += w;
    }
    #pragma unroll
    for (int o = 16; o; o >>= 1) den += __shfl_xor_sync(0xffffffffu, den, o);
    float inv = (cnt > 0) ? (1.0f / den) : 0.f;
    __syncwarp();

    // phase B: gather + FMA, 4 rows in flight, 2 accumulator sets
    float4 a0 = make_float4(0.f, 0.f, 0.f, 0.f);
    float4 a1 = make_float4(0.f, 0.f, 0.f, 0.f);
    int j = 0;
    for (; j + 4 <= cnt; j += 4) {
        int4 e4 = *reinterpret_cast<const int4*>(g_csr + base + j);
        float w0 = sw[ws][j];
        float w1 = sw[ws][j + 1];
        float w2 = sw[ws][j + 2];
        float w3 = sw[ws][j + 3];
        float4 f0 = __ldcs(reinterpret_cast<const float4*>(efeats) + (size_t)e4.x * 32 + lane);
        float4 f1 = __ldcs(reinterpret_cast<const float4*>(efeats) + (size_t)e4.y * 32 + lane);
        float4 f2 = __ldcs(reinterpret_cast<const float4*>(efeats) + (size_t)e4.z * 32 + lane);
        float4 f3 = __ldcs(reinterpret_cast<const float4*>(efeats) + (size_t)e4.w * 32 + lane);
        a0.x = fmaf(w0, f0.x, a0.x); a0.y = fmaf(w0, f0.y, a0.y);
        a0.z = fmaf(w0, f0.z, a0.z); a0.w = fmaf(w0, f0.w, a0.w);
        a1.x = fmaf(w1, f1.x, a1.x); a1.y = fmaf(w1, f1.y, a1.y);
        a1.z = fmaf(w1, f1.z, a1.z); a1.w = fmaf(w1, f1.w, a1.w);
        a0.x = fmaf(w2, f2.x, a0.x); a0.y = fmaf(w2, f2.y, a0.y);
        a0.z = fmaf(w2, f2.z, a0.z); a0.w = fmaf(w2, f2.w, a0.w);
        a1.x = fmaf(w3, f3.x, a1.x); a1.y = fmaf(w3, f3.y, a1.y);
        a1.z = fmaf(w3, f3.z, a1.z); a1.w = fmaf(w3, f3.w, a1.w);
    }
    for (; j < cnt; j++) {
        int e0 = g_csr[base + j];
        float w0 = sw[ws][j];
        float4 f0 = __ldcs(reinterpret_cast<const float4*>(efeats) + (size_t)e0 * 32 + lane);
        a0.x = fmaf(w0, f0.x, a0.x); a0.y = fmaf(w0, f0.y, a0.y);
        a0.z = fmaf(w0, f0.z, a0.z); a0.w = fmaf(w0, f0.w, a0.w);
    }
    a0.x = (a0.x + a1.x) * inv;
    a0.y = (a0.y + a1.y) * inv;
    a0.z = (a0.z + a1.z) * inv;
    a0.w = (a0.w + a1.w) * inv;

    size_t o = (size_t)n * 256 + 128 + lane * 4;
    split_store(a0.x, a0.y, g_xhi + o,     g_xlo + o);
    split_store(a0.z, a0.w, g_xhi + o + 2, g_xlo + o + 2);
}

// ---------------- both weight matrices -> fp16 (single launch) ----------------
__global__ void k_conv_w2(const float* __restrict__ W0, const float* __restrict__ W1) {
    int idx = blockIdx.x * blockDim.x + threadIdx.x;   // 2 x 8192 float4 groups
    if (idx >= 2 * 128 * 64) return;
    const float* W = (idx < 128 * 64) ? W0 : W1;
    __half* out = (idx < 128 * 64) ? g_wh0 : g_wh1;
    int l = idx & (128 * 64 - 1);
    float4 v = reinterpret_cast<const float4*>(W)[l];
    __half2 h01 = __halves2half2(__float2half_rn(v.x), __float2half_rn(v.y));
    __half2 h23 = __halves2half2(__float2half_rn(v.z), __float2half_rn(v.w));
    size_t o = (size_t)l * 4;
    *reinterpret_cast<__half2*>(out + o)     = h01;
    *reinterpret_cast<__half2*>(out + o + 2) = h23;
}

// ---------------- mma.sync fp16 2-term GEMM ----------------
// out = relu( (Xhi + Xlo) * Wh^T + b )
static constexpr int ROWB    = 80;
static constexpr int TILE_B  = 128 * ROWB;    // 10240
static constexpr int STAGE_B = 3 * TILE_B;    // 30720
static constexpr int GSMEM   = 2 * STAGE_B;   // 61440 -> 2 CTAs/SM

__global__ __launch_bounds__(256, 2) void k_gemm_mma(const __half* __restrict__ wh,
                                                     const float* __restrict__ bias,
                                                     float* __restrict__ out,
                                                     __half* __restrict__ xh,
                                                     __half* __restrict__ xl,
                                                     const float* __restrict__ awn) {
    extern __shared__ char smem[];
    __shared__ float sdot[2][128][2];
    const uint32_t sb = smem_u32(smem);
    const int tid  = threadIdx.x;
    const int wid  = tid >> 5;
    const int lane = tid & 31;
    const int bm   = blockIdx.x * 128;
    const int wm   = (wid & 3) * 32;
    const int wn   = (wid >> 2) * 64;

    float c[2][8][4];
    #pragma unroll
    for (int i = 0; i < 2; i++)
        #pragma unroll
        for (int j = 0; j < 8; j++)
            #pragma unroll
            for (int k = 0; k < 4; k++) c[i][j][k] = 0.f;

    auto load_chunk = [&](int kb, int st) {
        const uint32_t base = sb + st * STAGE_B;
        #pragma unroll
        for (int j = 0; j < 2; j++) {
            int idx = tid + j * 256;
            int row = idx >> 2;
            int grp = idx & 3;
            uint32_t soff = (uint32_t)(row * ROWB + grp * 16);
            int rg = bm + row;
            if (rg >= NN) rg = NN - 1;
            size_t ga = (size_t)rg * 256 + kb * 32 + grp * 8;
            cp16(base + 0 * TILE_B + soff, g_xhi + ga);
            cp16(base + 1 * TILE_B + soff, g_xlo + ga);
            size_t gw = (size_t)row * 256 + kb * 32 + grp * 8;
            cp16(base + 2 * TILE_B + soff, wh + gw);
        }
        cp_commit();
    };

    load_chunk(0, 0);

    const int g  = lane >> 3;
    const int l7 = lane & 7;

    #pragma unroll
    for (int kb = 0; kb < 8; kb++) {
        const int st = kb & 1;
        if (kb < 7) {
            load_chunk(kb + 1, st ^ 1);
            cp_wait<1>();
        } else {
            cp_wait<0>();
        }
        __syncthreads();

        const uint32_t baseA = sb + st * STAGE_B;
        const uint32_t baseB = baseA + 2 * TILE_B;

        #pragma unroll
        for (int ks = 0; ks < 2; ks++) {
            const int k0 = ks * 16;
            uint32_t ahi[2][4], alo[2][4];

            #pragma unroll
            for (int mi = 0; mi < 2; mi++) {
                int row = wm + mi * 16 + (g & 1) * 8 + l7;
                uint32_t kbyte = (uint32_t)((k0 + (g >> 1) * 8) * 2);
                uint32_t off = (uint32_t)(row * ROWB) + kbyte;
                ldsm_x4(ahi[mi][0], ahi[mi][1], ahi[mi][2], ahi[mi][3], baseA + off);
                ldsm_x4(alo[mi][0], alo[mi][1], alo[mi][2], alo[mi][3], baseA + TILE_B + off);
            }
            #pragma unroll
            for (int j2 = 0; j2 < 4; j2++) {
                int row = wn + j2 * 16 + (g >> 1) * 8 + l7;
                uint32_t kbyte = (uint32_t)((k0 + (g & 1) * 8) * 2);
                uint32_t off = (uint32_t)(row * ROWB) + kbyte;
                uint32_t bh[4];
                ldsm_x4(bh[0], bh[1], bh[2], bh[3], baseB + off);
                #pragma unroll
                for (int mi = 0; mi < 2; mi++) {
                    mma16816h(c[mi][2 * j2],     ahi[mi], bh);
                    mma16816h(c[mi][2 * j2],     alo[mi], bh);
                    mma16816h(c[mi][2 * j2 + 1], ahi[mi], bh + 2);
                    mma16816h(c[mi][2 * j2 + 1], alo[mi], bh + 2);
                }
            }
        }
        __syncthreads();
    }

    // epilogue
    #pragma unroll
    for (int mi = 0; mi < 2; mi++) {
        #pragma unroll
        for (int r = 0; r < 2; r++) {
            int mloc = wm + mi * 16 + (lane >> 2) + 8 * r;
            int m = bm + mloc;
            float ps = 0.f, pd = 0.f;
            #pragma unroll
            for (int nj = 0; nj < 8; nj++) {
                int n = wn + nj * 8 + (lane & 3) * 2;
                float2 bv = *reinterpret_cast<const float2*>(bias + n);
                float ox = fmaxf(c[mi][nj][2 * r + 0] + bv.x, 0.f);
                float oy = fmaxf(c[mi][nj][2 * r + 1] + bv.y, 0.f);
                if (m < NN) {
                    if (out)
                        *reinterpret_cast<float2*>(out + (size_t)m * DD + n) =
                            make_float2(ox, oy);
                    if (xh) {
                        size_t xo = (size_t)m * 256 + n;
                        split_store(ox, oy, xh + xo, xl + xo);
                    }
                }
                if (awn) {
                    float2 as = *reinterpret_cast<const float2*>(awn + n);
                    float2 ad = *reinterpret_cast<const float2*>(awn + 128 + n);
                    ps += ox * as.x + oy * as.y;
                    pd += ox * ad.x + oy * ad.y;
                }
            }
            if (awn) {
                ps += __shfl_xor_sync(0xffffffffu, ps, 1);
                ps += __shfl_xor_sync(0xffffffffu, ps, 2);
                pd += __shfl_xor_sync(0xffffffffu, pd, 1);
                pd += __shfl_xor_sync(0xffffffffu, pd, 2);
                if ((lane & 3) == 0) {
                    sdot[wid >> 2][mloc][0] = ps;
                    sdot[wid >> 2][mloc][1] = pd;
                }
            }
        }
    }
    if (awn) {
        __syncthreads();
        if (tid < 128) {
            int m = bm + tid;
            if (m < NN) {
                g_ssrc[m] = sdot[0][tid][0] + sdot[1][tid][0];
                g_sdst[m] = sdot[0][tid][1] + sdot[1][tid][1];
            }
        }
    }
}

// ---------------- launch ----------------
extern "C" void kernel_launch(void* const* d_in, const int* in_sizes, int n_in,
                              void* d_out, int out_size) {
    const float* nfeats = (const float*)d_in[0];
    const float* efeats = (const float*)d_in[1];
    const float* Ww0    = (const float*)d_in[2];
    const float* Wb0    = (const float*)d_in[3];
    const float* aw0    = (const float*)d_in[4];
    const float* ab0    = (const float*)d_in[5];
    const float* Ww1    = (const float*)d_in[6];
    const float* Wb1    = (const float*)d_in[7];
    const float* aw1    = (const float*)d_in[8];
    const float* ab1    = (const float*)d_in[9];
    const int*   src    = (const int*)d_in[10];
    const int*   dst    = (const int*)d_in[11];
    float* out = (float*)d_out;

    __half *wh0, *wh1, *xhi, *xlo;
    int* cntp = nullptr;
    cudaGetSymbolAddress((void**)&wh0, g_wh0);
    cudaGetSymbolAddress((void**)&wh1, g_wh1);
    cudaGetSymbolAddress((void**)&xhi, g_xhi);
    cudaGetSymbolAddress((void**)&xlo, g_xlo);
    cudaGetSymbolAddress((void**)&cntp, g_cnt);

    static bool init_done = false;
    static cudaStream_t s1 = nullptr;
    static cudaEvent_t ev0 = nullptr, evA = nullptr, evB = nullptr;
    if (!init_done) {
        cudaFuncSetAttribute(k_gemm_mma, cudaFuncAttributeMaxDynamicSharedMemorySize, GSMEM);
        cudaStreamCreateWithFlags(&s1, cudaStreamNonBlocking);
        cudaEventCreateWithFlags(&ev0, cudaEventDisableTiming);
        cudaEventCreateWithFlags(&evA, cudaEventDisableTiming);
        cudaEventCreateWithFlags(&evB, cudaEventDisableTiming);
        init_done = true;
    }

    const int E4B = (NE / 4 + 255) / 256;     // 625
    const int WB  = (NN + 7) / 8;             // 6250
    const int GB  = (NN + 127) / 128;         // 391
    const int CWB = (2 * 128 * 64 + 255) / 256;   // 64

    // fork side stream
    cudaEventRecord(ev0, 0);
    cudaStreamWaitEvent(s1, ev0, 0);

    // main: one-pass padded CSR (shared by both layers)
    cudaMemsetAsync(cntp, 0, NN * sizeof(int), 0);
    k_build<<<E4B, 256>>>(dst, src);

    // side: fused dots+conv of nfeats (gates softmax1), then both weight
    // conversions in one launch (gates gemm1 only)
    k_prep<<<WB, 256, 0, s1>>>(nfeats, aw0);
    cudaEventRecord(evA, s1);
    k_conv_w2<<<CWB, 256, 0, s1>>>(Ww0, Ww1);
    cudaEventRecord(evB, s1);

    // layer 1
    cudaStreamWaitEvent(0, evA, 0);
    k_softmax_z<<<WB, 256>>>(efeats, ab0);
    cudaStreamWaitEvent(0, evB, 0);
    k_gemm_mma<<<GB, 256, GSMEM>>>(wh0, Wb0, nullptr, xhi, xlo, aw1);

    // layer 2
    k_softmax_z<<<WB, 256>>>(efeats, ab1);
    k_gemm_mma<<<GB, 256, GSMEM>>>(wh1, Wb1, out, nullptr, nullptr, nullptr);
}